// round 13
// baseline (speedup 1.0000x reference)
#include <cuda_runtime.h>
#include <cuda_bf16.h>
#include <math.h>
#include <stdint.h>

#define N_NODES 30000
#define DIM     512
#define NE      300000
#define ET      (NE + N_NODES)     // 330000 edges incl self-loops
#define MPAD    30080              // 235 * 128
#define NPADD   (MPAD * DIM)

// ---------------- scratch (static __device__, no allocations) ----------------
__device__ __nv_bfloat16 g_ah[NPADD];       // A hi (dropout applied)
__device__ __nv_bfloat16 g_al[NPADD];       // A lo
__device__ __nv_bfloat16 g_wh[DIM * DIM];   // W^T hi  [n, k]
__device__ __nv_bfloat16 g_wl[DIM * DIM];   // W^T lo
__device__ float    g_h[NPADD];
__device__ float    g_as[N_NODES];
__device__ float    g_ad[N_NODES];
__device__ float    g_s[N_NODES];
__device__ int      g_cnt[N_NODES];
__device__ int      g_off[N_NODES + 1];
__device__ int      g_cur[N_NODES];
__device__ int2     g_pay[ET];              // compacted: {src, ee*2.5f}
__device__ double   g_colsum[DIM];
__device__ double   g_sumsq;
__device__ float    g_mu[DIM];
__device__ float    g_inv;

// ---------------- threefry2x32 (JAX-exact, 20 rounds), constexpr-capable ----
__host__ __device__ constexpr unsigned rotl32(unsigned v, int d) {
    return (v << d) | (v >> (32 - d));
}

struct U2 { unsigned a, b; };

__host__ __device__ constexpr U2 threefry2x32(
    unsigned k0, unsigned k1, unsigned c0, unsigned c1)
{
    unsigned ks0 = k0, ks1 = k1, ks2 = k0 ^ k1 ^ 0x1BD11BDAu;
    unsigned x0 = c0 + ks0;
    unsigned x1 = c1 + ks1;

#define TF_R4(a,b,c,d) \
    x0 += x1; x1 = rotl32(x1, a); x1 ^= x0; \
    x0 += x1; x1 = rotl32(x1, b); x1 ^= x0; \
    x0 += x1; x1 = rotl32(x1, c); x1 ^= x0; \
    x0 += x1; x1 = rotl32(x1, d); x1 ^= x0;

    TF_R4(13,15,26,6)   x0 += ks1; x1 += ks2 + 1u;
    TF_R4(17,29,16,24)  x0 += ks2; x1 += ks0 + 2u;
    TF_R4(13,15,26,6)   x0 += ks0; x1 += ks1 + 3u;
    TF_R4(17,29,16,24)  x0 += ks1; x1 += ks2 + 4u;
    TF_R4(13,15,26,6)   x0 += ks2; x1 += ks0 + 5u;
#undef TF_R4
    return U2{x0, x1};
}

constexpr U2 KFEAT = threefry2x32(0u, 42u, 0u, 0u);
constexpr U2 KATT  = threefry2x32(0u, 42u, 0u, 1u);

__device__ __forceinline__ unsigned tf_bits(unsigned k0, unsigned k1, unsigned idx) {
    U2 r = threefry2x32(k0, k1, 0u, idx);
    return r.a ^ r.b;
}
// attention-dropout keep test (exact float compare as reference)
__device__ __forceinline__ bool att_keep(unsigned j) {
    unsigned bits = tf_bits(KATT.a, KATT.b, j);
    float u = __uint_as_float((bits >> 9) | 0x3f800000u) - 1.0f;
    return u < 0.4f;
}

__device__ __forceinline__ uint32_t smem_u32(const void* p) {
    uint32_t a;
    asm("{ .reg .u64 t; cvta.to.shared.u64 t, %1; cvt.u32.u64 %0, t; }"
        : "=r"(a) : "l"(p));
    return a;
}
__device__ __forceinline__ void cp16(uint32_t dst, const void* src) {
    asm volatile("cp.async.cg.shared.global [%0], [%1], 16;"
                 :: "r"(dst), "l"(src) : "memory");
}

// ---------------- kernels ----------------
// fused init + W transpose/split
__global__ void k_prep_w(const float* __restrict__ W) {
    int i = blockIdx.x * blockDim.x + threadIdx.x;
    if (i < DIM * DIM) {
        int n = i >> 9, k = i & (DIM - 1);
        float v = W[k * DIM + n];
        __nv_bfloat16 h = __float2bfloat16(v);
        g_wh[i] = h;
        g_wl[i] = __float2bfloat16(v - __bfloat162float(h));
    }
    if (i < N_NODES) {
        g_cnt[i] = 0; g_s[i] = 0.0f;
        g_as[i] = 0.0f; g_ad[i] = 0.0f;
    }
    if (i < DIM) { g_colsum[i] = 0.0; }
    if (i == 0)  { g_sumsq = 0.0; }
}

// fused feature-dropout + bf16 hi/lo split, 4 elems/thread (ILP on threefry)
__global__ void k_prep_a(const float* __restrict__ x) {
    unsigned t  = blockIdx.x * blockDim.x + threadIdx.x;
    unsigned i0 = t * 4;
    if (i0 >= (unsigned)NPADD) return;

    unsigned hh[2] = {0u, 0u}, ll[2] = {0u, 0u};
    if (i0 < (unsigned)(N_NODES * DIM)) {       // region is 4-divisible
        float4 xv = *(const float4*)(x + i0);
        float vs[4] = {xv.x, xv.y, xv.z, xv.w};
        unsigned mb[4];
#pragma unroll
        for (int j = 0; j < 4; j++) mb[j] = tf_bits(KFEAT.a, KFEAT.b, i0 + j);
#pragma unroll
        for (int j = 0; j < 4; j++) {
            // keep  <=>  u < 0.5  <=>  top bit of bits is 0
            float v = (mb[j] & 0x80000000u) ? 0.0f : vs[j] * 2.0f;
            __nv_bfloat16 h = __float2bfloat16(v);
            __nv_bfloat16 l = __float2bfloat16(v - __bfloat162float(h));
            unsigned hu = (unsigned)__bfloat16_as_ushort(h);
            unsigned lu = (unsigned)__bfloat16_as_ushort(l);
            hh[j >> 1] |= hu << ((j & 1) * 16);
            ll[j >> 1] |= lu << ((j & 1) * 16);
        }
    }
    *(uint2*)((unsigned short*)g_ah + i0) = make_uint2(hh[0], hh[1]);
    *(uint2*)((unsigned short*)g_al + i0) = make_uint2(ll[0], ll[1]);
}

// ---------------- mma.sync bf16 GEMM, single-loop 3-product -----------------
// CTA tile 128x128, 8 warps (2x4), warp tile 64x32, BK=32.
// Per K-chunk load Ah,Al,Wh,Wl once; acc += ah*wh + ah*wl + al*wh.
// Fused epilogue: h row-dots with att_src/att_dst -> g_as/g_ad (atomic).
#define LDT 40                      // padded smem lead dim (bf16 elems)
#define GBK 32
#define NCH (DIM / GBK)             // 16 chunks
#define TILE_B (128 * LDT * 2)      // 10240 B per tile
#define STG_B  (4 * TILE_B)         // Ah,Al,Bh,Bl per stage = 40960 B
#define SM_GEMM (2 * STG_B)         // 81920 B

__global__ void __launch_bounds__(256, 2) k_gemm_mma(
    const float* __restrict__ att_src,
    const float* __restrict__ att_dst)
{
    extern __shared__ char smem[];

    const int tid  = threadIdx.x;
    const int wid  = tid >> 5;
    const int lane = tid & 31;
    const int brow = blockIdx.y * 128;
    const int bcol = blockIdx.x * 128;
    const int wm   = (wid >> 2) * 64;
    const int wn   = (wid & 3) * 32;

    const int lr = tid >> 2;              // 0..63 (x2 -> 128 rows)
    const int lc = (tid & 3) * 8;         // bf16 col group

    const uint32_t s0 = smem_u32(smem);

    float acc[4][4][4];
#pragma unroll
    for (int mt = 0; mt < 4; mt++)
#pragma unroll
        for (int nt = 0; nt < 4; nt++)
#pragma unroll
            for (int c = 0; c < 4; c++) acc[mt][nt][c] = 0.0f;

    const int a_row  = wm + (lane & 15);
    const int a_koff = (lane >> 4) * 8;
    const int b_row  = wn + (lane & 15);

    auto load_chunk = [&](int c, int st) {
        int k0 = c * GBK;
        uint32_t base = s0 + st * STG_B;
#pragma unroll
        for (int it = 0; it < 2; it++) {
            int r = lr + it * 64;
            uint32_t off = (r * LDT + lc) * 2;
            size_t ga = (size_t)(brow + r) * DIM + k0 + lc;
            size_t gb = (size_t)(bcol + r) * DIM + k0 + lc;
            cp16(base + 0 * TILE_B + off, g_ah + ga);
            cp16(base + 1 * TILE_B + off, g_al + ga);
            cp16(base + 2 * TILE_B + off, g_wh + gb);
            cp16(base + 3 * TILE_B + off, g_wl + gb);
        }
    };

    load_chunk(0, 0);
    asm volatile("cp.async.commit_group;" ::: "memory");

    for (int c = 0; c < NCH; c++) {
        int st = c & 1;
        if (c + 1 < NCH) {
            asm volatile("cp.async.wait_group 0;" ::: "memory");
            __syncthreads();
            load_chunk(c + 1, st ^ 1);
            asm volatile("cp.async.commit_group;" ::: "memory");
        } else {
            asm volatile("cp.async.wait_group 0;" ::: "memory");
            __syncthreads();
        }

        const __nv_bfloat16* Ah = (const __nv_bfloat16*)(smem + st * STG_B);
        const __nv_bfloat16* Al = (const __nv_bfloat16*)(smem + st * STG_B + TILE_B);
        const __nv_bfloat16* Bh = (const __nv_bfloat16*)(smem + st * STG_B + 2 * TILE_B);
        const __nv_bfloat16* Bl = (const __nv_bfloat16*)(smem + st * STG_B + 3 * TILE_B);

#pragma unroll
        for (int ks = 0; ks < 2; ks++) {
            int k16 = ks * 16;
            uint32_t bh[4][2], bl[4][2];
#pragma unroll
            for (int nt2 = 0; nt2 < 2; nt2++) {
                uint32_t r0, r1, r2, r3;
                uint32_t addr = smem_u32(&Bh[(b_row + nt2 * 16) * LDT + k16 + a_koff]);
                asm volatile(
                    "ldmatrix.sync.aligned.m8n8.x4.shared.b16 {%0,%1,%2,%3}, [%4];"
                    : "=r"(r0), "=r"(r1), "=r"(r2), "=r"(r3) : "r"(addr));
                bh[2 * nt2][0] = r0; bh[2 * nt2 + 1][0] = r1;
                bh[2 * nt2][1] = r2; bh[2 * nt2 + 1][1] = r3;
                addr = smem_u32(&Bl[(b_row + nt2 * 16) * LDT + k16 + a_koff]);
                asm volatile(
                    "ldmatrix.sync.aligned.m8n8.x4.shared.b16 {%0,%1,%2,%3}, [%4];"
                    : "=r"(r0), "=r"(r1), "=r"(r2), "=r"(r3) : "r"(addr));
                bl[2 * nt2][0] = r0; bl[2 * nt2 + 1][0] = r1;
                bl[2 * nt2][1] = r2; bl[2 * nt2 + 1][1] = r3;
            }
            uint32_t a[4][4];
#pragma unroll
            for (int mt = 0; mt < 4; mt++) {
                uint32_t addr = smem_u32(&Ah[(a_row + mt * 16) * LDT + k16 + a_koff]);
                asm volatile(
                    "ldmatrix.sync.aligned.m8n8.x4.shared.b16 {%0,%1,%2,%3}, [%4];"
                    : "=r"(a[mt][0]), "=r"(a[mt][1]), "=r"(a[mt][2]), "=r"(a[mt][3])
                    : "r"(addr));
            }
#pragma unroll
            for (int mt = 0; mt < 4; mt++)
#pragma unroll
                for (int nt = 0; nt < 4; nt++) {
                    asm volatile(
                        "mma.sync.aligned.m16n8k16.row.col.f32.bf16.bf16.f32 "
                        "{%0,%1,%2,%3}, {%4,%5,%6,%7}, {%8,%9}, {%0,%1,%2,%3};"
                        : "+f"(acc[mt][nt][0]), "+f"(acc[mt][nt][1]),
                          "+f"(acc[mt][nt][2]), "+f"(acc[mt][nt][3])
                        : "r"(a[mt][0]), "r"(a[mt][1]), "r"(a[mt][2]), "r"(a[mt][3]),
                          "r"(bh[nt][0]), "r"(bh[nt][1]));
                    asm volatile(
                        "mma.sync.aligned.m16n8k16.row.col.f32.bf16.bf16.f32 "
                        "{%0,%1,%2,%3}, {%4,%5,%6,%7}, {%8,%9}, {%0,%1,%2,%3};"
                        : "+f"(acc[mt][nt][0]), "+f"(acc[mt][nt][1]),
                          "+f"(acc[mt][nt][2]), "+f"(acc[mt][nt][3])
                        : "r"(a[mt][0]), "r"(a[mt][1]), "r"(a[mt][2]), "r"(a[mt][3]),
                          "r"(bl[nt][0]), "r"(bl[nt][1]));
                }
#pragma unroll
            for (int mt = 0; mt < 4; mt++) {
                uint32_t addr = smem_u32(&Al[(a_row + mt * 16) * LDT + k16 + a_koff]);
                asm volatile(
                    "ldmatrix.sync.aligned.m8n8.x4.shared.b16 {%0,%1,%2,%3}, [%4];"
                    : "=r"(a[mt][0]), "=r"(a[mt][1]), "=r"(a[mt][2]), "=r"(a[mt][3])
                    : "r"(addr));
            }
#pragma unroll
            for (int mt = 0; mt < 4; mt++)
#pragma unroll
                for (int nt = 0; nt < 4; nt++) {
                    asm volatile(
                        "mma.sync.aligned.m16n8k16.row.col.f32.bf16.bf16.f32 "
                        "{%0,%1,%2,%3}, {%4,%5,%6,%7}, {%8,%9}, {%0,%1,%2,%3};"
                        : "+f"(acc[mt][nt][0]), "+f"(acc[mt][nt][1]),
                          "+f"(acc[mt][nt][2]), "+f"(acc[mt][nt][3])
                        : "r"(a[mt][0]), "r"(a[mt][1]), "r"(a[mt][2]), "r"(a[mt][3]),
                          "r"(bh[nt][0]), "r"(bh[nt][1]));
                }
        }
        if (c + 1 < NCH) __syncthreads();
        // barrier orders "all warps finished reading stage st" before the
        // NEXT iteration's cp.async writes into it.
    }

    // epilogue: write fp32 result + fused att dot products
    const int group = lane >> 2;
    const int tg    = lane & 3;

    float as0[4], as1[4], ad0[4], ad1[4];
#pragma unroll
    for (int nt = 0; nt < 4; nt++) {
        int col = bcol + wn + nt * 8 + tg * 2;
        as0[nt] = att_src[col];  as1[nt] = att_src[col + 1];
        ad0[nt] = att_dst[col];  ad1[nt] = att_dst[col + 1];
    }

#pragma unroll
    for (int mt = 0; mt < 4; mt++) {
        int m0 = brow + wm + mt * 16 + group;
        float v0s = 0.f, v8s = 0.f, v0d = 0.f, v8d = 0.f;
#pragma unroll
        for (int nt = 0; nt < 4; nt++) {
            int col = bcol + wn + nt * 8 + tg * 2;
            *(float2*)(g_h + (size_t)m0 * DIM + col) =
                make_float2(acc[mt][nt][0], acc[mt][nt][1]);
            *(float2*)(g_h + (size_t)(m0 + 8) * DIM + col) =
                make_float2(acc[mt][nt][2], acc[mt][nt][3]);
            v0s += acc[mt][nt][0] * as0[nt] + acc[mt][nt][1] * as1[nt];
            v8s += acc[mt][nt][2] * as0[nt] + acc[mt][nt][3] * as1[nt];
            v0d += acc[mt][nt][0] * ad0[nt] + acc[mt][nt][1] * ad1[nt];
            v8d += acc[mt][nt][2] * ad0[nt] + acc[mt][nt][3] * ad1[nt];
        }
#pragma unroll
        for (int o = 1; o <= 2; o <<= 1) {
            v0s += __shfl_xor_sync(0xffffffffu, v0s, o);
            v8s += __shfl_xor_sync(0xffffffffu, v8s, o);
            v0d += __shfl_xor_sync(0xffffffffu, v0d, o);
            v8d += __shfl_xor_sync(0xffffffffu, v8d, o);
        }
        if (tg == 0) {
            if (m0 < N_NODES) {
                atomicAdd(&g_as[m0], v0s);
                atomicAdd(&g_ad[m0], v0d);
            }
            if (m0 + 8 < N_NODES) {
                atomicAdd(&g_as[m0 + 8], v8s);
                atomicAdd(&g_ad[m0 + 8], v8d);
            }
        }
    }
}

// kept-edge counts only (no float math)
__global__ void k_edge(const int* __restrict__ ei) {
    int j = blockIdx.x * blockDim.x + threadIdx.x;
    if (j >= ET) return;
    if (att_keep((unsigned)j)) {
        int dst = (j < NE) ? ei[NE + j] : (j - NE);
        atomicAdd(&g_cnt[dst], 1);
    }
}

// single-pass scan: 1024 threads, contiguous 30-element chunk per thread
#define SCHUNK 30   // 1024 * 30 = 30720 >= N_NODES
__global__ void k_scan() {
    __shared__ int wsum[32];
    int tid  = threadIdx.x;
    int lane = tid & 31;
    int wq   = tid >> 5;
    int base = tid * SCHUNK;

    int loc[SCHUNK];
    int s = 0;
#pragma unroll
    for (int k = 0; k < SCHUNK; k++) {
        int i = base + k;
        int v = (i < N_NODES) ? g_cnt[i] : 0;
        loc[k] = s;
        s += v;
    }
    // block exclusive scan of per-thread sums
    int incl = s;
#pragma unroll
    for (int o = 1; o < 32; o <<= 1) {
        int t = __shfl_up_sync(0xffffffffu, incl, o);
        if (lane >= o) incl += t;
    }
    if (lane == 31) wsum[wq] = incl;
    __syncthreads();
    if (wq == 0) {
        int t2 = wsum[lane];
#pragma unroll
        for (int o = 1; o < 32; o <<= 1) {
            int t = __shfl_up_sync(0xffffffffu, t2, o);
            if (lane >= o) t2 += t;
        }
        wsum[lane] = t2;
    }
    __syncthreads();
    int off = ((wq > 0) ? wsum[wq - 1] : 0) + incl - s;   // exclusive for thread
#pragma unroll
    for (int k = 0; k < SCHUNK; k++) {
        int i = base + k;
        if (i < N_NODES) {
            int ex = off + loc[k];
            g_off[i] = ex;
            g_cur[i] = ex;
        }
    }
    if (tid == 1023) g_off[N_NODES] = off + s;
}

// softmax numerators + compacted CSR fill (payload {src, ee*2.5} kept only)
__global__ void k_fill(const int* __restrict__ ei) {
    int j = blockIdx.x * blockDim.x + threadIdx.x;
    if (j >= ET) return;
    int src = (j < NE) ? ei[j]      : (j - NE);
    int dst = (j < NE) ? ei[NE + j] : (j - NE);
    float e = g_as[src] + g_ad[dst];
    e = (e >= 0.0f) ? e : 0.2f * e;                 // LeakyReLU(0.2)
    float ee = __expf(e);
    atomicAdd(&g_s[dst], ee);
    if (att_keep((unsigned)j)) {
        int pos = atomicAdd(&g_cur[dst], 1);
        g_pay[pos] = make_int2(src, __float_as_int(ee * 2.5f));
    }
}

// block per dst node; smem-staged payload; 128 threads x float4 = 512 cols
__global__ void __launch_bounds__(128) k_agg(
    const float* __restrict__ bias,
    float* __restrict__ out)
{
    __shared__ int2 pay_sh[128];
    int dst = blockIdx.x;
    int tid = threadIdx.x;
    int c   = tid * 4;
    float inv = 1.0f / (g_s[dst] + 1e-16f);
    float4 acc = make_float4(0.f, 0.f, 0.f, 0.f);
    int beg = g_off[dst], end = g_off[dst + 1];
    for (int chunk = beg; chunk < end; chunk += 128) {
        int n = min(128, end - chunk);
        if (tid < n) pay_sh[tid] = g_pay[chunk + tid];
        __syncthreads();
#pragma unroll 4
        for (int p = 0; p < n; p++) {
            int2 rec = pay_sh[p];
            float w = __int_as_float(rec.y) * inv;
            float4 hv = *(const float4*)(g_h + (size_t)rec.x * DIM + c);
            acc.x = fmaf(w, hv.x, acc.x);
            acc.y = fmaf(w, hv.y, acc.y);
            acc.z = fmaf(w, hv.z, acc.z);
            acc.w = fmaf(w, hv.w, acc.w);
        }
        __syncthreads();
    }
    float4 bv = *(const float4*)(bias + c);
    acc.x += bv.x; acc.y += bv.y; acc.z += bv.z; acc.w += bv.w;
    *(float4*)(out + (size_t)dst * DIM + c) = acc;
}

// column sums + total sum of squares (for PairNorm)
#define CM_ROWS 235
__global__ void __launch_bounds__(256) k_colmean(const float* __restrict__ out) {
    __shared__ double ssq_sh[256];
    int tid = threadIdx.x;
    int r0 = blockIdx.x * CM_ROWS;
    int r1 = min(N_NODES, r0 + CM_ROWS);
    float s1 = 0.0f, s2 = 0.0f;
    double ssq = 0.0;
    for (int r = r0; r < r1; r++) {
        float v1 = out[(size_t)r * DIM + tid];
        float v2 = out[(size_t)r * DIM + tid + 256];
        s1 += v1; s2 += v2;
        ssq += (double)v1 * v1 + (double)v2 * v2;
    }
    atomicAdd(&g_colsum[tid],       (double)s1);
    atomicAdd(&g_colsum[tid + 256], (double)s2);
    ssq_sh[tid] = ssq;
    __syncthreads();
    for (int o = 128; o > 0; o >>= 1) {
        if (tid < o) ssq_sh[tid] += ssq_sh[tid + o];
        __syncthreads();
    }
    if (tid == 0) atomicAdd(&g_sumsq, ssq_sh[0]);
}

__global__ void k_stats() {
    __shared__ double sh[512];
    int t = threadIdx.x;
    double mu = g_colsum[t] / (double)N_NODES;
    g_mu[t] = (float)mu;
    sh[t] = mu * mu;
    __syncthreads();
    for (int o = 256; o > 0; o >>= 1) {
        if (t < o) sh[t] += sh[t + o];
        __syncthreads();
    }
    if (t == 0) {
        double var = g_sumsq / (double)N_NODES - sh[0];
        g_inv = (float)(1.0 / sqrt(1e-6 + var));
    }
}

__global__ void k_final(float* __restrict__ out) {
    unsigned i = (blockIdx.x * blockDim.x + threadIdx.x) * 4;
    if (i >= (unsigned)(N_NODES * DIM)) return;
    float4 v  = *(const float4*)(out + i);
    float4 mu = *(const float4*)(g_mu + (i & (DIM - 1)));
    float inv = g_inv;
    v.x = fmaxf((v.x - mu.x) * inv, 0.0f);
    v.y = fmaxf((v.y - mu.y) * inv, 0.0f);
    v.z = fmaxf((v.z - mu.z) * inv, 0.0f);
    v.w = fmaxf((v.w - mu.w) * inv, 0.0f);
    *(float4*)(out + i) = v;
}

// ---------------- launch ----------------
extern "C" void kernel_launch(void* const* d_in, const int* in_sizes, int n_in,
                              void* d_out, int out_size)
{
    const float* x       = (const float*)d_in[0];
    const int*   ei      = (const int*)  d_in[1];
    const float* W       = (const float*)d_in[2];
    const float* att_src = (const float*)d_in[3];
    const float* att_dst = (const float*)d_in[4];
    const float* bias    = (const float*)d_in[5];
    float*       out     = (float*)d_out;
    (void)in_sizes; (void)n_in; (void)out_size;

    cudaFuncSetAttribute(k_gemm_mma,
                         cudaFuncAttributeMaxDynamicSharedMemorySize, SM_GEMM);

    k_prep_w<<<(DIM * DIM + 255) / 256, 256>>>(W);
    k_prep_a<<<(NPADD / 4 + 255) / 256, 256>>>(x);
    k_gemm_mma<<<dim3(4, 235), 256, SM_GEMM>>>(att_src, att_dst);
    k_edge<<<(ET + 255) / 256, 256>>>(ei);
    k_scan<<<1, 1024>>>();
    k_fill<<<(ET + 255) / 256, 256>>>(ei);
    k_agg<<<N_NODES, 128>>>(bias, out);
    k_colmean<<<(N_NODES + CM_ROWS - 1) / CM_ROWS, 256>>>(out);
    k_stats<<<1, 512>>>();
    k_final<<<(N_NODES * DIM / 4 + 255) / 256, 256>>>(out);
}

// round 14
// speedup vs baseline: 1.0025x; 1.0025x over previous
#include <cuda_runtime.h>
#include <cuda_bf16.h>
#include <math.h>
#include <stdint.h>

#define N_NODES 30000
#define DIM     512
#define NE      300000
#define ET      (NE + N_NODES)     // 330000 edges incl self-loops
#define MPAD    30080              // 235 * 128
#define NPADD   (MPAD * DIM)

// ---------------- scratch (static __device__, no allocations) ----------------
__device__ __nv_bfloat16 g_ah[NPADD];       // A hi (dropout applied)
__device__ __nv_bfloat16 g_al[NPADD];       // A lo
__device__ __nv_bfloat16 g_wh[DIM * DIM];   // W^T hi  [n, k]
__device__ __nv_bfloat16 g_wl[DIM * DIM];   // W^T lo
__device__ float    g_h[NPADD];
__device__ float    g_as[N_NODES];
__device__ float    g_ad[N_NODES];
__device__ float    g_s[N_NODES];
__device__ int      g_cnt[N_NODES];
__device__ int      g_off[N_NODES + 1];
__device__ int      g_cur[N_NODES];
__device__ int2     g_pay[ET];              // compacted: {src, ee*2.5f}
__device__ double   g_colsum[DIM];
__device__ double   g_sumsq;
__device__ float    g_mu[DIM];
__device__ float    g_inv;

// ---------------- threefry2x32 (JAX-exact, 20 rounds), constexpr-capable ----
__host__ __device__ constexpr unsigned rotl32(unsigned v, int d) {
    return (v << d) | (v >> (32 - d));
}

struct U2 { unsigned a, b; };

__host__ __device__ constexpr U2 threefry2x32(
    unsigned k0, unsigned k1, unsigned c0, unsigned c1)
{
    unsigned ks0 = k0, ks1 = k1, ks2 = k0 ^ k1 ^ 0x1BD11BDAu;
    unsigned x0 = c0 + ks0;
    unsigned x1 = c1 + ks1;

#define TF_R4(a,b,c,d) \
    x0 += x1; x1 = rotl32(x1, a); x1 ^= x0; \
    x0 += x1; x1 = rotl32(x1, b); x1 ^= x0; \
    x0 += x1; x1 = rotl32(x1, c); x1 ^= x0; \
    x0 += x1; x1 = rotl32(x1, d); x1 ^= x0;

    TF_R4(13,15,26,6)   x0 += ks1; x1 += ks2 + 1u;
    TF_R4(17,29,16,24)  x0 += ks2; x1 += ks0 + 2u;
    TF_R4(13,15,26,6)   x0 += ks0; x1 += ks1 + 3u;
    TF_R4(17,29,16,24)  x0 += ks1; x1 += ks2 + 4u;
    TF_R4(13,15,26,6)   x0 += ks2; x1 += ks0 + 5u;
#undef TF_R4
    return U2{x0, x1};
}

constexpr U2 KFEAT = threefry2x32(0u, 42u, 0u, 0u);
constexpr U2 KATT  = threefry2x32(0u, 42u, 0u, 1u);

__device__ __forceinline__ unsigned tf_bits(unsigned k0, unsigned k1, unsigned idx) {
    U2 r = threefry2x32(k0, k1, 0u, idx);
    return r.a ^ r.b;
}
// attention-dropout keep test (exact float compare as reference)
__device__ __forceinline__ bool att_keep(unsigned j) {
    unsigned bits = tf_bits(KATT.a, KATT.b, j);
    float u = __uint_as_float((bits >> 9) | 0x3f800000u) - 1.0f;
    return u < 0.4f;
}

__device__ __forceinline__ uint32_t smem_u32(const void* p) {
    uint32_t a;
    asm("{ .reg .u64 t; cvta.to.shared.u64 t, %1; cvt.u32.u64 %0, t; }"
        : "=r"(a) : "l"(p));
    return a;
}
__device__ __forceinline__ void cp16(uint32_t dst, const void* src) {
    asm volatile("cp.async.cg.shared.global [%0], [%1], 16;"
                 :: "r"(dst), "l"(src) : "memory");
}

// ---------------- kernels ----------------
// fused init + W transpose/split
__global__ void k_prep_w(const float* __restrict__ W) {
    int i = blockIdx.x * blockDim.x + threadIdx.x;
    if (i < DIM * DIM) {
        int n = i >> 9, k = i & (DIM - 1);
        float v = W[k * DIM + n];
        __nv_bfloat16 h = __float2bfloat16(v);
        g_wh[i] = h;
        g_wl[i] = __float2bfloat16(v - __bfloat162float(h));
    }
    if (i < N_NODES) {
        g_cnt[i] = 0; g_s[i] = 0.0f;
        g_as[i] = 0.0f; g_ad[i] = 0.0f;
    }
    if (i < DIM) { g_colsum[i] = 0.0; }
    if (i == 0)  { g_sumsq = 0.0; }
}

// fused feature-dropout + bf16 hi/lo split, 4 elems/thread (ILP on threefry)
__global__ void k_prep_a(const float* __restrict__ x) {
    unsigned t  = blockIdx.x * blockDim.x + threadIdx.x;
    unsigned i0 = t * 4;
    if (i0 >= (unsigned)NPADD) return;

    unsigned hh[2] = {0u, 0u}, ll[2] = {0u, 0u};
    if (i0 < (unsigned)(N_NODES * DIM)) {       // region is 4-divisible
        float4 xv = *(const float4*)(x + i0);
        float vs[4] = {xv.x, xv.y, xv.z, xv.w};
        unsigned mb[4];
#pragma unroll
        for (int j = 0; j < 4; j++) mb[j] = tf_bits(KFEAT.a, KFEAT.b, i0 + j);
#pragma unroll
        for (int j = 0; j < 4; j++) {
            // keep  <=>  u < 0.5  <=>  top bit of bits is 0
            float v = (mb[j] & 0x80000000u) ? 0.0f : vs[j] * 2.0f;
            __nv_bfloat16 h = __float2bfloat16(v);
            __nv_bfloat16 l = __float2bfloat16(v - __bfloat162float(h));
            unsigned hu = (unsigned)__bfloat16_as_ushort(h);
            unsigned lu = (unsigned)__bfloat16_as_ushort(l);
            hh[j >> 1] |= hu << ((j & 1) * 16);
            ll[j >> 1] |= lu << ((j & 1) * 16);
        }
    }
    *(uint2*)((unsigned short*)g_ah + i0) = make_uint2(hh[0], hh[1]);
    *(uint2*)((unsigned short*)g_al + i0) = make_uint2(ll[0], ll[1]);
}

// ---------------- mma.sync bf16 GEMM, single-loop 3-product -----------------
// CTA tile 128x128, 8 warps (2x4), warp tile 64x32, BK=32.
// Per K-chunk load Ah,Al,Wh,Wl once; acc += ah*wh + ah*wl + al*wh.
// Fused epilogue: h row-dots with att_src/att_dst -> g_as/g_ad (atomic).
#define LDT 40                      // padded smem lead dim (bf16 elems)
#define GBK 32
#define NCH (DIM / GBK)             // 16 chunks
#define TILE_B (128 * LDT * 2)      // 10240 B per tile
#define STG_B  (4 * TILE_B)         // Ah,Al,Bh,Bl per stage = 40960 B
#define SM_GEMM (2 * STG_B)         // 81920 B

__global__ void __launch_bounds__(256, 2) k_gemm_mma(
    const float* __restrict__ att_src,
    const float* __restrict__ att_dst)
{
    extern __shared__ char smem[];

    const int tid  = threadIdx.x;
    const int wid  = tid >> 5;
    const int lane = tid & 31;
    const int brow = blockIdx.y * 128;
    const int bcol = blockIdx.x * 128;
    const int wm   = (wid >> 2) * 64;
    const int wn   = (wid & 3) * 32;

    const int lr = tid >> 2;              // 0..63 (x2 -> 128 rows)
    const int lc = (tid & 3) * 8;         // bf16 col group

    const uint32_t s0 = smem_u32(smem);

    float acc[4][4][4];
#pragma unroll
    for (int mt = 0; mt < 4; mt++)
#pragma unroll
        for (int nt = 0; nt < 4; nt++)
#pragma unroll
            for (int c = 0; c < 4; c++) acc[mt][nt][c] = 0.0f;

    const int a_row  = wm + (lane & 15);
    const int a_koff = (lane >> 4) * 8;
    const int b_row  = wn + (lane & 15);

    auto load_chunk = [&](int c, int st) {
        int k0 = c * GBK;
        uint32_t base = s0 + st * STG_B;
#pragma unroll
        for (int it = 0; it < 2; it++) {
            int r = lr + it * 64;
            uint32_t off = (r * LDT + lc) * 2;
            size_t ga = (size_t)(brow + r) * DIM + k0 + lc;
            size_t gb = (size_t)(bcol + r) * DIM + k0 + lc;
            cp16(base + 0 * TILE_B + off, g_ah + ga);
            cp16(base + 1 * TILE_B + off, g_al + ga);
            cp16(base + 2 * TILE_B + off, g_wh + gb);
            cp16(base + 3 * TILE_B + off, g_wl + gb);
        }
    };

    load_chunk(0, 0);
    asm volatile("cp.async.commit_group;" ::: "memory");

    for (int c = 0; c < NCH; c++) {
        int st = c & 1;
        if (c + 1 < NCH) {
            asm volatile("cp.async.wait_group 0;" ::: "memory");
            __syncthreads();
            load_chunk(c + 1, st ^ 1);
            asm volatile("cp.async.commit_group;" ::: "memory");
        } else {
            asm volatile("cp.async.wait_group 0;" ::: "memory");
            __syncthreads();
        }

        const __nv_bfloat16* Ah = (const __nv_bfloat16*)(smem + st * STG_B);
        const __nv_bfloat16* Al = (const __nv_bfloat16*)(smem + st * STG_B + TILE_B);
        const __nv_bfloat16* Bh = (const __nv_bfloat16*)(smem + st * STG_B + 2 * TILE_B);
        const __nv_bfloat16* Bl = (const __nv_bfloat16*)(smem + st * STG_B + 3 * TILE_B);

#pragma unroll
        for (int ks = 0; ks < 2; ks++) {
            int k16 = ks * 16;
            uint32_t bh[4][2], bl[4][2];
#pragma unroll
            for (int nt2 = 0; nt2 < 2; nt2++) {
                uint32_t r0, r1, r2, r3;
                uint32_t addr = smem_u32(&Bh[(b_row + nt2 * 16) * LDT + k16 + a_koff]);
                asm volatile(
                    "ldmatrix.sync.aligned.m8n8.x4.shared.b16 {%0,%1,%2,%3}, [%4];"
                    : "=r"(r0), "=r"(r1), "=r"(r2), "=r"(r3) : "r"(addr));
                bh[2 * nt2][0] = r0; bh[2 * nt2 + 1][0] = r1;
                bh[2 * nt2][1] = r2; bh[2 * nt2 + 1][1] = r3;
                addr = smem_u32(&Bl[(b_row + nt2 * 16) * LDT + k16 + a_koff]);
                asm volatile(
                    "ldmatrix.sync.aligned.m8n8.x4.shared.b16 {%0,%1,%2,%3}, [%4];"
                    : "=r"(r0), "=r"(r1), "=r"(r2), "=r"(r3) : "r"(addr));
                bl[2 * nt2][0] = r0; bl[2 * nt2 + 1][0] = r1;
                bl[2 * nt2][1] = r2; bl[2 * nt2 + 1][1] = r3;
            }
            uint32_t a[4][4];
#pragma unroll
            for (int mt = 0; mt < 4; mt++) {
                uint32_t addr = smem_u32(&Ah[(a_row + mt * 16) * LDT + k16 + a_koff]);
                asm volatile(
                    "ldmatrix.sync.aligned.m8n8.x4.shared.b16 {%0,%1,%2,%3}, [%4];"
                    : "=r"(a[mt][0]), "=r"(a[mt][1]), "=r"(a[mt][2]), "=r"(a[mt][3])
                    : "r"(addr));
            }
#pragma unroll
            for (int mt = 0; mt < 4; mt++)
#pragma unroll
                for (int nt = 0; nt < 4; nt++) {
                    asm volatile(
                        "mma.sync.aligned.m16n8k16.row.col.f32.bf16.bf16.f32 "
                        "{%0,%1,%2,%3}, {%4,%5,%6,%7}, {%8,%9}, {%0,%1,%2,%3};"
                        : "+f"(acc[mt][nt][0]), "+f"(acc[mt][nt][1]),
                          "+f"(acc[mt][nt][2]), "+f"(acc[mt][nt][3])
                        : "r"(a[mt][0]), "r"(a[mt][1]), "r"(a[mt][2]), "r"(a[mt][3]),
                          "r"(bh[nt][0]), "r"(bh[nt][1]));
                    asm volatile(
                        "mma.sync.aligned.m16n8k16.row.col.f32.bf16.bf16.f32 "
                        "{%0,%1,%2,%3}, {%4,%5,%6,%7}, {%8,%9}, {%0,%1,%2,%3};"
                        : "+f"(acc[mt][nt][0]), "+f"(acc[mt][nt][1]),
                          "+f"(acc[mt][nt][2]), "+f"(acc[mt][nt][3])
                        : "r"(a[mt][0]), "r"(a[mt][1]), "r"(a[mt][2]), "r"(a[mt][3]),
                          "r"(bl[nt][0]), "r"(bl[nt][1]));
                }
#pragma unroll
            for (int mt = 0; mt < 4; mt++) {
                uint32_t addr = smem_u32(&Al[(a_row + mt * 16) * LDT + k16 + a_koff]);
                asm volatile(
                    "ldmatrix.sync.aligned.m8n8.x4.shared.b16 {%0,%1,%2,%3}, [%4];"
                    : "=r"(a[mt][0]), "=r"(a[mt][1]), "=r"(a[mt][2]), "=r"(a[mt][3])
                    : "r"(addr));
            }
#pragma unroll
            for (int mt = 0; mt < 4; mt++)
#pragma unroll
                for (int nt = 0; nt < 4; nt++) {
                    asm volatile(
                        "mma.sync.aligned.m16n8k16.row.col.f32.bf16.bf16.f32 "
                        "{%0,%1,%2,%3}, {%4,%5,%6,%7}, {%8,%9}, {%0,%1,%2,%3};"
                        : "+f"(acc[mt][nt][0]), "+f"(acc[mt][nt][1]),
                          "+f"(acc[mt][nt][2]), "+f"(acc[mt][nt][3])
                        : "r"(a[mt][0]), "r"(a[mt][1]), "r"(a[mt][2]), "r"(a[mt][3]),
                          "r"(bh[nt][0]), "r"(bh[nt][1]));
                }
        }
        if (c + 1 < NCH) __syncthreads();
        // barrier orders "all warps finished reading stage st" before the
        // NEXT iteration's cp.async writes into it.
    }

    // epilogue: write fp32 result + fused att dot products
    const int group = lane >> 2;
    const int tg    = lane & 3;

    float as0[4], as1[4], ad0[4], ad1[4];
#pragma unroll
    for (int nt = 0; nt < 4; nt++) {
        int col = bcol + wn + nt * 8 + tg * 2;
        as0[nt] = att_src[col];  as1[nt] = att_src[col + 1];
        ad0[nt] = att_dst[col];  ad1[nt] = att_dst[col + 1];
    }

#pragma unroll
    for (int mt = 0; mt < 4; mt++) {
        int m0 = brow + wm + mt * 16 + group;
        float v0s = 0.f, v8s = 0.f, v0d = 0.f, v8d = 0.f;
#pragma unroll
        for (int nt = 0; nt < 4; nt++) {
            int col = bcol + wn + nt * 8 + tg * 2;
            *(float2*)(g_h + (size_t)m0 * DIM + col) =
                make_float2(acc[mt][nt][0], acc[mt][nt][1]);
            *(float2*)(g_h + (size_t)(m0 + 8) * DIM + col) =
                make_float2(acc[mt][nt][2], acc[mt][nt][3]);
            v0s += acc[mt][nt][0] * as0[nt] + acc[mt][nt][1] * as1[nt];
            v8s += acc[mt][nt][2] * as0[nt] + acc[mt][nt][3] * as1[nt];
            v0d += acc[mt][nt][0] * ad0[nt] + acc[mt][nt][1] * ad1[nt];
            v8d += acc[mt][nt][2] * ad0[nt] + acc[mt][nt][3] * ad1[nt];
        }
#pragma unroll
        for (int o = 1; o <= 2; o <<= 1) {
            v0s += __shfl_xor_sync(0xffffffffu, v0s, o);
            v8s += __shfl_xor_sync(0xffffffffu, v8s, o);
            v0d += __shfl_xor_sync(0xffffffffu, v0d, o);
            v8d += __shfl_xor_sync(0xffffffffu, v8d, o);
        }
        if (tg == 0) {
            if (m0 < N_NODES) {
                atomicAdd(&g_as[m0], v0s);
                atomicAdd(&g_ad[m0], v0d);
            }
            if (m0 + 8 < N_NODES) {
                atomicAdd(&g_as[m0 + 8], v8s);
                atomicAdd(&g_ad[m0 + 8], v8d);
            }
        }
    }
}

// kept-edge counts only (no float math)
__global__ void k_edge(const int* __restrict__ ei) {
    int j = blockIdx.x * blockDim.x + threadIdx.x;
    if (j >= ET) return;
    if (att_keep((unsigned)j)) {
        int dst = (j < NE) ? ei[NE + j] : (j - NE);
        atomicAdd(&g_cnt[dst], 1);
    }
}

// single-pass scan: 1024 threads, contiguous 30-element chunk per thread
#define SCHUNK 30   // 1024 * 30 = 30720 >= N_NODES
__global__ void k_scan() {
    __shared__ int wsum[32];
    int tid  = threadIdx.x;
    int lane = tid & 31;
    int wq   = tid >> 5;
    int base = tid * SCHUNK;

    int loc[SCHUNK];
    int s = 0;
#pragma unroll
    for (int k = 0; k < SCHUNK; k++) {
        int i = base + k;
        int v = (i < N_NODES) ? g_cnt[i] : 0;
        loc[k] = s;
        s += v;
    }
    // block exclusive scan of per-thread sums
    int incl = s;
#pragma unroll
    for (int o = 1; o < 32; o <<= 1) {
        int t = __shfl_up_sync(0xffffffffu, incl, o);
        if (lane >= o) incl += t;
    }
    if (lane == 31) wsum[wq] = incl;
    __syncthreads();
    if (wq == 0) {
        int t2 = wsum[lane];
#pragma unroll
        for (int o = 1; o < 32; o <<= 1) {
            int t = __shfl_up_sync(0xffffffffu, t2, o);
            if (lane >= o) t2 += t;
        }
        wsum[lane] = t2;
    }
    __syncthreads();
    int off = ((wq > 0) ? wsum[wq - 1] : 0) + incl - s;   // exclusive for thread
#pragma unroll
    for (int k = 0; k < SCHUNK; k++) {
        int i = base + k;
        if (i < N_NODES) {
            int ex = off + loc[k];
            g_off[i] = ex;
            g_cur[i] = ex;
        }
    }
    if (tid == 1023) g_off[N_NODES] = off + s;
}

// softmax numerators + compacted CSR fill (payload {src, ee*2.5} kept only)
__global__ void k_fill(const int* __restrict__ ei) {
    int j = blockIdx.x * blockDim.x + threadIdx.x;
    if (j >= ET) return;
    int src = (j < NE) ? ei[j]      : (j - NE);
    int dst = (j < NE) ? ei[NE + j] : (j - NE);
    float e = g_as[src] + g_ad[dst];
    e = (e >= 0.0f) ? e : 0.2f * e;                 // LeakyReLU(0.2)
    float ee = __expf(e);
    atomicAdd(&g_s[dst], ee);
    if (att_keep((unsigned)j)) {
        int pos = atomicAdd(&g_cur[dst], 1);
        g_pay[pos] = make_int2(src, __float_as_int(ee * 2.5f));
    }
}

// block per dst node; 128 threads x float4 = 512 cols (simple per-record loop;
// mean kept degree ~4.4 so smem staging/barriers don't pay)
__global__ void __launch_bounds__(128) k_agg(
    const float* __restrict__ bias,
    float* __restrict__ out)
{
    int dst = blockIdx.x;
    int c   = threadIdx.x * 4;
    float inv = 1.0f / (g_s[dst] + 1e-16f);
    float4 acc = make_float4(0.f, 0.f, 0.f, 0.f);
    int beg = g_off[dst], end = g_off[dst + 1];
    for (int p = beg; p < end; p++) {
        int2 rec = g_pay[p];
        float w = __int_as_float(rec.y) * inv;
        float4 hv = *(const float4*)(g_h + (size_t)rec.x * DIM + c);
        acc.x = fmaf(w, hv.x, acc.x);
        acc.y = fmaf(w, hv.y, acc.y);
        acc.z = fmaf(w, hv.z, acc.z);
        acc.w = fmaf(w, hv.w, acc.w);
    }
    float4 bv = *(const float4*)(bias + c);
    acc.x += bv.x; acc.y += bv.y; acc.z += bv.z; acc.w += bv.w;
    *(float4*)(out + (size_t)dst * DIM + c) = acc;
}

// column sums + total sum of squares (for PairNorm)
#define CM_ROWS 235
__global__ void __launch_bounds__(256) k_colmean(const float* __restrict__ out) {
    __shared__ double ssq_sh[256];
    int tid = threadIdx.x;
    int r0 = blockIdx.x * CM_ROWS;
    int r1 = min(N_NODES, r0 + CM_ROWS);
    float s1 = 0.0f, s2 = 0.0f;
    double ssq = 0.0;
    for (int r = r0; r < r1; r++) {
        float v1 = out[(size_t)r * DIM + tid];
        float v2 = out[(size_t)r * DIM + tid + 256];
        s1 += v1; s2 += v2;
        ssq += (double)v1 * v1 + (double)v2 * v2;
    }
    atomicAdd(&g_colsum[tid],       (double)s1);
    atomicAdd(&g_colsum[tid + 256], (double)s2);
    ssq_sh[tid] = ssq;
    __syncthreads();
    for (int o = 128; o > 0; o >>= 1) {
        if (tid < o) ssq_sh[tid] += ssq_sh[tid + o];
        __syncthreads();
    }
    if (tid == 0) atomicAdd(&g_sumsq, ssq_sh[0]);
}

__global__ void k_stats() {
    __shared__ double sh[512];
    int t = threadIdx.x;
    double mu = g_colsum[t] / (double)N_NODES;
    g_mu[t] = (float)mu;
    sh[t] = mu * mu;
    __syncthreads();
    for (int o = 256; o > 0; o >>= 1) {
        if (t < o) sh[t] += sh[t + o];
        __syncthreads();
    }
    if (t == 0) {
        double var = g_sumsq / (double)N_NODES - sh[0];
        g_inv = (float)(1.0 / sqrt(1e-6 + var));
    }
}

__global__ void k_final(float* __restrict__ out) {
    unsigned i = (blockIdx.x * blockDim.x + threadIdx.x) * 4;
    if (i >= (unsigned)(N_NODES * DIM)) return;
    float4 v  = *(const float4*)(out + i);
    float4 mu = *(const float4*)(g_mu + (i & (DIM - 1)));
    float inv = g_inv;
    v.x = fmaxf((v.x - mu.x) * inv, 0.0f);
    v.y = fmaxf((v.y - mu.y) * inv, 0.0f);
    v.z = fmaxf((v.z - mu.z) * inv, 0.0f);
    v.w = fmaxf((v.w - mu.w) * inv, 0.0f);
    *(float4*)(out + i) = v;
}

// ---------------- launch ----------------
extern "C" void kernel_launch(void* const* d_in, const int* in_sizes, int n_in,
                              void* d_out, int out_size)
{
    const float* x       = (const float*)d_in[0];
    const int*   ei      = (const int*)  d_in[1];
    const float* W       = (const float*)d_in[2];
    const float* att_src = (const float*)d_in[3];
    const float* att_dst = (const float*)d_in[4];
    const float* bias    = (const float*)d_in[5];
    float*       out     = (float*)d_out;
    (void)in_sizes; (void)n_in; (void)out_size;

    cudaFuncSetAttribute(k_gemm_mma,
                         cudaFuncAttributeMaxDynamicSharedMemorySize, SM_GEMM);

    k_prep_w<<<(DIM * DIM + 255) / 256, 256>>>(W);
    k_prep_a<<<(NPADD / 4 + 255) / 256, 256>>>(x);
    k_gemm_mma<<<dim3(4, 235), 256, SM_GEMM>>>(att_src, att_dst);
    k_edge<<<(ET + 255) / 256, 256>>>(ei);
    k_scan<<<1, 1024>>>();
    k_fill<<<(ET + 255) / 256, 256>>>(ei);
    k_agg<<<N_NODES, 128>>>(bias, out);
    k_colmean<<<(N_NODES + CM_ROWS - 1) / CM_ROWS, 256>>>(out);
    k_stats<<<1, 512>>>();
    k_final<<<(N_NODES * DIM / 4 + 255) / 256, 256>>>(out);
}

// round 15
// speedup vs baseline: 1.0383x; 1.0358x over previous
#include <cuda_runtime.h>
#include <cuda_bf16.h>
#include <math.h>
#include <stdint.h>

#define N_NODES 30000
#define DIM     512
#define NE      300000
#define ET      (NE + N_NODES)     // 330000 edges incl self-loops
#define MPAD    30080              // 235 * 128
#define NPADD   (MPAD * DIM)

// ---------------- scratch (static __device__, no allocations) ----------------
__device__ __nv_bfloat16 g_ah[NPADD];       // A hi (dropout applied)
__device__ __nv_bfloat16 g_al[NPADD];       // A lo
__device__ __nv_bfloat16 g_wh[DIM * DIM];   // W^T hi  [n, k]
__device__ __nv_bfloat16 g_wl[DIM * DIM];   // W^T lo
__device__ float    g_h[NPADD];
__device__ float    g_as[N_NODES];
__device__ float    g_ad[N_NODES];
__device__ float    g_e[ET];
__device__ unsigned char g_keep[ET];
__device__ float    g_s[N_NODES];
__device__ int      g_cnt[N_NODES];
__device__ int      g_off[N_NODES + 1];
__device__ int      g_cur[N_NODES];
__device__ int2     g_pay[ET];              // compacted: {src, ee*2.5f}
__device__ double   g_colsum[DIM];
__device__ double   g_sumsq;
__device__ float    g_mu[DIM];
__device__ float    g_inv;

// ---------------- threefry2x32 (JAX-exact, 20 rounds), constexpr-capable ----
__host__ __device__ constexpr unsigned rotl32(unsigned v, int d) {
    return (v << d) | (v >> (32 - d));
}

struct U2 { unsigned a, b; };

__host__ __device__ constexpr U2 threefry2x32(
    unsigned k0, unsigned k1, unsigned c0, unsigned c1)
{
    unsigned ks0 = k0, ks1 = k1, ks2 = k0 ^ k1 ^ 0x1BD11BDAu;
    unsigned x0 = c0 + ks0;
    unsigned x1 = c1 + ks1;

#define TF_R4(a,b,c,d) \
    x0 += x1; x1 = rotl32(x1, a); x1 ^= x0; \
    x0 += x1; x1 = rotl32(x1, b); x1 ^= x0; \
    x0 += x1; x1 = rotl32(x1, c); x1 ^= x0; \
    x0 += x1; x1 = rotl32(x1, d); x1 ^= x0;

    TF_R4(13,15,26,6)   x0 += ks1; x1 += ks2 + 1u;
    TF_R4(17,29,16,24)  x0 += ks2; x1 += ks0 + 2u;
    TF_R4(13,15,26,6)   x0 += ks0; x1 += ks1 + 3u;
    TF_R4(17,29,16,24)  x0 += ks1; x1 += ks2 + 4u;
    TF_R4(13,15,26,6)   x0 += ks2; x1 += ks0 + 5u;
#undef TF_R4
    return U2{x0, x1};
}

constexpr U2 KFEAT = threefry2x32(0u, 42u, 0u, 0u);
constexpr U2 KATT  = threefry2x32(0u, 42u, 0u, 1u);

__device__ __forceinline__ unsigned tf_bits(unsigned k0, unsigned k1, unsigned idx) {
    U2 r = threefry2x32(k0, k1, 0u, idx);
    return r.a ^ r.b;
}
// attention-dropout keep test (exact float compare as reference)
__device__ __forceinline__ bool att_keep(unsigned j) {
    unsigned bits = tf_bits(KATT.a, KATT.b, j);
    float u = __uint_as_float((bits >> 9) | 0x3f800000u) - 1.0f;
    return u < 0.4f;
}

__device__ __forceinline__ uint32_t smem_u32(const void* p) {
    uint32_t a;
    asm("{ .reg .u64 t; cvta.to.shared.u64 t, %1; cvt.u32.u64 %0, t; }"
        : "=r"(a) : "l"(p));
    return a;
}
__device__ __forceinline__ void cp16(uint32_t dst, const void* src) {
    asm volatile("cp.async.cg.shared.global [%0], [%1], 16;"
                 :: "r"(dst), "l"(src) : "memory");
}

// ---------------- kernels ----------------
// fused init + W transpose/split
__global__ void k_prep_w(const float* __restrict__ W) {
    int i = blockIdx.x * blockDim.x + threadIdx.x;
    if (i < DIM * DIM) {
        int n = i >> 9, k = i & (DIM - 1);
        float v = W[k * DIM + n];
        __nv_bfloat16 h = __float2bfloat16(v);
        g_wh[i] = h;
        g_wl[i] = __float2bfloat16(v - __bfloat162float(h));
    }
    if (i < N_NODES) {
        g_cnt[i] = 0; g_s[i] = 0.0f;
        g_as[i] = 0.0f; g_ad[i] = 0.0f;
    }
    if (i < DIM) { g_colsum[i] = 0.0; }
    if (i == 0)  { g_sumsq = 0.0; }
}

// fused feature-dropout + bf16 hi/lo split, 4 elems/thread (ILP on threefry)
__global__ void k_prep_a(const float* __restrict__ x) {
    unsigned t  = blockIdx.x * blockDim.x + threadIdx.x;
    unsigned i0 = t * 4;
    if (i0 >= (unsigned)NPADD) return;

    unsigned hh[2] = {0u, 0u}, ll[2] = {0u, 0u};
    if (i0 < (unsigned)(N_NODES * DIM)) {       // region is 4-divisible
        float4 xv = *(const float4*)(x + i0);
        float vs[4] = {xv.x, xv.y, xv.z, xv.w};
        unsigned mb[4];
#pragma unroll
        for (int j = 0; j < 4; j++) mb[j] = tf_bits(KFEAT.a, KFEAT.b, i0 + j);
#pragma unroll
        for (int j = 0; j < 4; j++) {
            // keep  <=>  u < 0.5  <=>  top bit of bits is 0
            float v = (mb[j] & 0x80000000u) ? 0.0f : vs[j] * 2.0f;
            __nv_bfloat16 h = __float2bfloat16(v);
            __nv_bfloat16 l = __float2bfloat16(v - __bfloat162float(h));
            unsigned hu = (unsigned)__bfloat16_as_ushort(h);
            unsigned lu = (unsigned)__bfloat16_as_ushort(l);
            hh[j >> 1] |= hu << ((j & 1) * 16);
            ll[j >> 1] |= lu << ((j & 1) * 16);
        }
    }
    *(uint2*)((unsigned short*)g_ah + i0) = make_uint2(hh[0], hh[1]);
    *(uint2*)((unsigned short*)g_al + i0) = make_uint2(ll[0], ll[1]);
}

// ---------------- mma.sync bf16 GEMM, single-loop 3-product -----------------
// CTA tile 128x128, 8 warps (2x4), warp tile 64x32, BK=32.
// Per K-chunk load Ah,Al,Wh,Wl once; acc += ah*wh + ah*wl + al*wh.
// Fused epilogue: h row-dots with att_src/att_dst -> g_as/g_ad (atomic).
#define LDT 40                      // padded smem lead dim (bf16 elems)
#define GBK 32
#define NCH (DIM / GBK)             // 16 chunks
#define TILE_B (128 * LDT * 2)      // 10240 B per tile
#define STG_B  (4 * TILE_B)         // Ah,Al,Bh,Bl per stage = 40960 B
#define SM_GEMM (2 * STG_B)         // 81920 B

__global__ void __launch_bounds__(256, 2) k_gemm_mma(
    const float* __restrict__ att_src,
    const float* __restrict__ att_dst)
{
    extern __shared__ char smem[];

    const int tid  = threadIdx.x;
    const int wid  = tid >> 5;
    const int lane = tid & 31;
    const int brow = blockIdx.y * 128;
    const int bcol = blockIdx.x * 128;
    const int wm   = (wid >> 2) * 64;
    const int wn   = (wid & 3) * 32;

    const int lr = tid >> 2;              // 0..63 (x2 -> 128 rows)
    const int lc = (tid & 3) * 8;         // bf16 col group

    const uint32_t s0 = smem_u32(smem);

    float acc[4][4][4];
#pragma unroll
    for (int mt = 0; mt < 4; mt++)
#pragma unroll
        for (int nt = 0; nt < 4; nt++)
#pragma unroll
            for (int c = 0; c < 4; c++) acc[mt][nt][c] = 0.0f;

    const int a_row  = wm + (lane & 15);
    const int a_koff = (lane >> 4) * 8;
    const int b_row  = wn + (lane & 15);

    auto load_chunk = [&](int c, int st) {
        int k0 = c * GBK;
        uint32_t base = s0 + st * STG_B;
#pragma unroll
        for (int it = 0; it < 2; it++) {
            int r = lr + it * 64;
            uint32_t off = (r * LDT + lc) * 2;
            size_t ga = (size_t)(brow + r) * DIM + k0 + lc;
            size_t gb = (size_t)(bcol + r) * DIM + k0 + lc;
            cp16(base + 0 * TILE_B + off, g_ah + ga);
            cp16(base + 1 * TILE_B + off, g_al + ga);
            cp16(base + 2 * TILE_B + off, g_wh + gb);
            cp16(base + 3 * TILE_B + off, g_wl + gb);
        }
    };

    load_chunk(0, 0);
    asm volatile("cp.async.commit_group;" ::: "memory");

    for (int c = 0; c < NCH; c++) {
        int st = c & 1;
        if (c + 1 < NCH) {
            asm volatile("cp.async.wait_group 0;" ::: "memory");
            __syncthreads();
            load_chunk(c + 1, st ^ 1);
            asm volatile("cp.async.commit_group;" ::: "memory");
        } else {
            asm volatile("cp.async.wait_group 0;" ::: "memory");
            __syncthreads();
        }

        const __nv_bfloat16* Ah = (const __nv_bfloat16*)(smem + st * STG_B);
        const __nv_bfloat16* Al = (const __nv_bfloat16*)(smem + st * STG_B + TILE_B);
        const __nv_bfloat16* Bh = (const __nv_bfloat16*)(smem + st * STG_B + 2 * TILE_B);
        const __nv_bfloat16* Bl = (const __nv_bfloat16*)(smem + st * STG_B + 3 * TILE_B);

#pragma unroll
        for (int ks = 0; ks < 2; ks++) {
            int k16 = ks * 16;
            uint32_t bh[4][2], bl[4][2];
#pragma unroll
            for (int nt2 = 0; nt2 < 2; nt2++) {
                uint32_t r0, r1, r2, r3;
                uint32_t addr = smem_u32(&Bh[(b_row + nt2 * 16) * LDT + k16 + a_koff]);
                asm volatile(
                    "ldmatrix.sync.aligned.m8n8.x4.shared.b16 {%0,%1,%2,%3}, [%4];"
                    : "=r"(r0), "=r"(r1), "=r"(r2), "=r"(r3) : "r"(addr));
                bh[2 * nt2][0] = r0; bh[2 * nt2 + 1][0] = r1;
                bh[2 * nt2][1] = r2; bh[2 * nt2 + 1][1] = r3;
                addr = smem_u32(&Bl[(b_row + nt2 * 16) * LDT + k16 + a_koff]);
                asm volatile(
                    "ldmatrix.sync.aligned.m8n8.x4.shared.b16 {%0,%1,%2,%3}, [%4];"
                    : "=r"(r0), "=r"(r1), "=r"(r2), "=r"(r3) : "r"(addr));
                bl[2 * nt2][0] = r0; bl[2 * nt2 + 1][0] = r1;
                bl[2 * nt2][1] = r2; bl[2 * nt2 + 1][1] = r3;
            }
            uint32_t a[4][4];
#pragma unroll
            for (int mt = 0; mt < 4; mt++) {
                uint32_t addr = smem_u32(&Ah[(a_row + mt * 16) * LDT + k16 + a_koff]);
                asm volatile(
                    "ldmatrix.sync.aligned.m8n8.x4.shared.b16 {%0,%1,%2,%3}, [%4];"
                    : "=r"(a[mt][0]), "=r"(a[mt][1]), "=r"(a[mt][2]), "=r"(a[mt][3])
                    : "r"(addr));
            }
#pragma unroll
            for (int mt = 0; mt < 4; mt++)
#pragma unroll
                for (int nt = 0; nt < 4; nt++) {
                    asm volatile(
                        "mma.sync.aligned.m16n8k16.row.col.f32.bf16.bf16.f32 "
                        "{%0,%1,%2,%3}, {%4,%5,%6,%7}, {%8,%9}, {%0,%1,%2,%3};"
                        : "+f"(acc[mt][nt][0]), "+f"(acc[mt][nt][1]),
                          "+f"(acc[mt][nt][2]), "+f"(acc[mt][nt][3])
                        : "r"(a[mt][0]), "r"(a[mt][1]), "r"(a[mt][2]), "r"(a[mt][3]),
                          "r"(bh[nt][0]), "r"(bh[nt][1]));
                    asm volatile(
                        "mma.sync.aligned.m16n8k16.row.col.f32.bf16.bf16.f32 "
                        "{%0,%1,%2,%3}, {%4,%5,%6,%7}, {%8,%9}, {%0,%1,%2,%3};"
                        : "+f"(acc[mt][nt][0]), "+f"(acc[mt][nt][1]),
                          "+f"(acc[mt][nt][2]), "+f"(acc[mt][nt][3])
                        : "r"(a[mt][0]), "r"(a[mt][1]), "r"(a[mt][2]), "r"(a[mt][3]),
                          "r"(bl[nt][0]), "r"(bl[nt][1]));
                }
#pragma unroll
            for (int mt = 0; mt < 4; mt++) {
                uint32_t addr = smem_u32(&Al[(a_row + mt * 16) * LDT + k16 + a_koff]);
                asm volatile(
                    "ldmatrix.sync.aligned.m8n8.x4.shared.b16 {%0,%1,%2,%3}, [%4];"
                    : "=r"(a[mt][0]), "=r"(a[mt][1]), "=r"(a[mt][2]), "=r"(a[mt][3])
                    : "r"(addr));
            }
#pragma unroll
            for (int mt = 0; mt < 4; mt++)
#pragma unroll
                for (int nt = 0; nt < 4; nt++) {
                    asm volatile(
                        "mma.sync.aligned.m16n8k16.row.col.f32.bf16.bf16.f32 "
                        "{%0,%1,%2,%3}, {%4,%5,%6,%7}, {%8,%9}, {%0,%1,%2,%3};"
                        : "+f"(acc[mt][nt][0]), "+f"(acc[mt][nt][1]),
                          "+f"(acc[mt][nt][2]), "+f"(acc[mt][nt][3])
                        : "r"(a[mt][0]), "r"(a[mt][1]), "r"(a[mt][2]), "r"(a[mt][3]),
                          "r"(bh[nt][0]), "r"(bh[nt][1]));
                }
        }
        if (c + 1 < NCH) __syncthreads();
        // barrier orders "all warps finished reading stage st" before the
        // NEXT iteration's cp.async writes into it.
    }

    // epilogue: write fp32 result + fused att dot products
    const int group = lane >> 2;
    const int tg    = lane & 3;

    float as0[4], as1[4], ad0[4], ad1[4];
#pragma unroll
    for (int nt = 0; nt < 4; nt++) {
        int col = bcol + wn + nt * 8 + tg * 2;
        as0[nt] = att_src[col];  as1[nt] = att_src[col + 1];
        ad0[nt] = att_dst[col];  ad1[nt] = att_dst[col + 1];
    }

#pragma unroll
    for (int mt = 0; mt < 4; mt++) {
        int m0 = brow + wm + mt * 16 + group;
        float v0s = 0.f, v8s = 0.f, v0d = 0.f, v8d = 0.f;
#pragma unroll
        for (int nt = 0; nt < 4; nt++) {
            int col = bcol + wn + nt * 8 + tg * 2;
            *(float2*)(g_h + (size_t)m0 * DIM + col) =
                make_float2(acc[mt][nt][0], acc[mt][nt][1]);
            *(float2*)(g_h + (size_t)(m0 + 8) * DIM + col) =
                make_float2(acc[mt][nt][2], acc[mt][nt][3]);
            v0s += acc[mt][nt][0] * as0[nt] + acc[mt][nt][1] * as1[nt];
            v8s += acc[mt][nt][2] * as0[nt] + acc[mt][nt][3] * as1[nt];
            v0d += acc[mt][nt][0] * ad0[nt] + acc[mt][nt][1] * ad1[nt];
            v8d += acc[mt][nt][2] * ad0[nt] + acc[mt][nt][3] * ad1[nt];
        }
#pragma unroll
        for (int o = 1; o <= 2; o <<= 1) {
            v0s += __shfl_xor_sync(0xffffffffu, v0s, o);
            v8s += __shfl_xor_sync(0xffffffffu, v8s, o);
            v0d += __shfl_xor_sync(0xffffffffu, v0d, o);
            v8d += __shfl_xor_sync(0xffffffffu, v8d, o);
        }
        if (tg == 0) {
            if (m0 < N_NODES) {
                atomicAdd(&g_as[m0], v0s);
                atomicAdd(&g_ad[m0], v0d);
            }
            if (m0 + 8 < N_NODES) {
                atomicAdd(&g_as[m0 + 8], v8s);
                atomicAdd(&g_ad[m0 + 8], v8d);
            }
        }
    }
}

// edge logits + keep mask + kept-edge counts
__global__ void k_edge(const int* __restrict__ ei) {
    int j = blockIdx.x * blockDim.x + threadIdx.x;
    if (j >= ET) return;
    int src = (j < NE) ? ei[j]      : (j - NE);
    int dst = (j < NE) ? ei[NE + j] : (j - NE);
    float e = g_as[src] + g_ad[dst];
    e = (e >= 0.0f) ? e : 0.2f * e;                 // LeakyReLU(0.2)
    g_e[j] = e;
    bool kp = att_keep((unsigned)j);
    g_keep[j] = kp ? 1 : 0;
    if (kp) atomicAdd(&g_cnt[dst], 1);
}

// warp-shuffle block scan: 3 barriers per 1024-element step (coalesced loads)
__global__ void k_scan() {
    __shared__ int wsum[32];
    __shared__ int wtot;
    int tid  = threadIdx.x;
    int lane = tid & 31;
    int wq   = tid >> 5;
    int carry = 0;
    for (int base = 0; base < N_NODES; base += 1024) {
        int i = base + tid;
        int v = (i < N_NODES) ? g_cnt[i] : 0;
        int incl = v;
#pragma unroll
        for (int o = 1; o < 32; o <<= 1) {
            int t = __shfl_up_sync(0xffffffffu, incl, o);
            if (lane >= o) incl += t;
        }
        if (lane == 31) wsum[wq] = incl;
        __syncthreads();
        if (wq == 0) {
            int s = wsum[lane];
#pragma unroll
            for (int o = 1; o < 32; o <<= 1) {
                int t = __shfl_up_sync(0xffffffffu, s, o);
                if (lane >= o) s += t;
            }
            wsum[lane] = s;
            if (lane == 31) wtot = s;
        }
        __syncthreads();
        int woff = (wq > 0) ? wsum[wq - 1] : 0;
        if (i < N_NODES) {
            int ex = carry + woff + incl - v;
            g_off[i] = ex;
            g_cur[i] = ex;
        }
        carry += wtot;
        __syncthreads();
    }
    if (tid == 0) g_off[N_NODES] = carry;
}

// softmax numerators + compacted CSR fill (payload {src, ee*2.5} kept only)
__global__ void k_fill(const int* __restrict__ ei) {
    int j = blockIdx.x * blockDim.x + threadIdx.x;
    if (j >= ET) return;
    int dst = (j < NE) ? ei[NE + j] : (j - NE);
    float ee = __expf(g_e[j]);
    atomicAdd(&g_s[dst], ee);
    if (g_keep[j]) {
        int src = (j < NE) ? ei[j] : (j - NE);
        int pos = atomicAdd(&g_cur[dst], 1);
        g_pay[pos] = make_int2(src, __float_as_int(ee * 2.5f));
    }
}

// block per dst node; 128 threads x float4 = 512 cols
__global__ void __launch_bounds__(128) k_agg(
    const float* __restrict__ bias,
    float* __restrict__ out)
{
    int dst = blockIdx.x;
    int c   = threadIdx.x * 4;
    float inv = 1.0f / (g_s[dst] + 1e-16f);
    float4 acc = make_float4(0.f, 0.f, 0.f, 0.f);
    int beg = g_off[dst], end = g_off[dst + 1];
    for (int p = beg; p < end; p++) {
        int2 rec = g_pay[p];
        float w = __int_as_float(rec.y) * inv;
        float4 hv = *(const float4*)(g_h + (size_t)rec.x * DIM + c);
        acc.x = fmaf(w, hv.x, acc.x);
        acc.y = fmaf(w, hv.y, acc.y);
        acc.z = fmaf(w, hv.z, acc.z);
        acc.w = fmaf(w, hv.w, acc.w);
    }
    float4 bv = *(const float4*)(bias + c);
    acc.x += bv.x; acc.y += bv.y; acc.z += bv.z; acc.w += bv.w;
    *(float4*)(out + (size_t)dst * DIM + c) = acc;
}

// column sums + total sum of squares (for PairNorm)
#define CM_ROWS 235
__global__ void __launch_bounds__(256) k_colmean(const float* __restrict__ out) {
    __shared__ double ssq_sh[256];
    int tid = threadIdx.x;
    int r0 = blockIdx.x * CM_ROWS;
    int r1 = min(N_NODES, r0 + CM_ROWS);
    float s1 = 0.0f, s2 = 0.0f;
    double ssq = 0.0;
    for (int r = r0; r < r1; r++) {
        float v1 = out[(size_t)r * DIM + tid];
        float v2 = out[(size_t)r * DIM + tid + 256];
        s1 += v1; s2 += v2;
        ssq += (double)v1 * v1 + (double)v2 * v2;
    }
    atomicAdd(&g_colsum[tid],       (double)s1);
    atomicAdd(&g_colsum[tid + 256], (double)s2);
    ssq_sh[tid] = ssq;
    __syncthreads();
    for (int o = 128; o > 0; o >>= 1) {
        if (tid < o) ssq_sh[tid] += ssq_sh[tid + o];
        __syncthreads();
    }
    if (tid == 0) atomicAdd(&g_sumsq, ssq_sh[0]);
}

__global__ void k_stats() {
    __shared__ double sh[512];
    int t = threadIdx.x;
    double mu = g_colsum[t] / (double)N_NODES;
    g_mu[t] = (float)mu;
    sh[t] = mu * mu;
    __syncthreads();
    for (int o = 256; o > 0; o >>= 1) {
        if (t < o) sh[t] += sh[t + o];
        __syncthreads();
    }
    if (t == 0) {
        double var = g_sumsq / (double)N_NODES - sh[0];
        g_inv = (float)(1.0 / sqrt(1e-6 + var));
    }
}

__global__ void k_final(float* __restrict__ out) {
    unsigned i = (blockIdx.x * blockDim.x + threadIdx.x) * 4;
    if (i >= (unsigned)(N_NODES * DIM)) return;
    float4 v  = *(const float4*)(out + i);
    float4 mu = *(const float4*)(g_mu + (i & (DIM - 1)));
    float inv = g_inv;
    v.x = fmaxf((v.x - mu.x) * inv, 0.0f);
    v.y = fmaxf((v.y - mu.y) * inv, 0.0f);
    v.z = fmaxf((v.z - mu.z) * inv, 0.0f);
    v.w = fmaxf((v.w - mu.w) * inv, 0.0f);
    *(float4*)(out + i) = v;
}

// ---------------- launch ----------------
extern "C" void kernel_launch(void* const* d_in, const int* in_sizes, int n_in,
                              void* d_out, int out_size)
{
    const float* x       = (const float*)d_in[0];
    const int*   ei      = (const int*)  d_in[1];
    const float* W       = (const float*)d_in[2];
    const float* att_src = (const float*)d_in[3];
    const float* att_dst = (const float*)d_in[4];
    const float* bias    = (const float*)d_in[5];
    float*       out     = (float*)d_out;
    (void)in_sizes; (void)n_in; (void)out_size;

    cudaFuncSetAttribute(k_gemm_mma,
                         cudaFuncAttributeMaxDynamicSharedMemorySize, SM_GEMM);

    k_prep_w<<<(DIM * DIM + 255) / 256, 256>>>(W);
    k_prep_a<<<(NPADD / 4 + 255) / 256, 256>>>(x);
    k_gemm_mma<<<dim3(4, 235), 256, SM_GEMM>>>(att_src, att_dst);
    k_edge<<<(ET + 255) / 256, 256>>>(ei);
    k_scan<<<1, 1024>>>();
    k_fill<<<(ET + 255) / 256, 256>>>(ei);
    k_agg<<<N_NODES, 128>>>(bias, out);
    k_colmean<<<(N_NODES + CM_ROWS - 1) / CM_ROWS, 256>>>(out);
    k_stats<<<1, 512>>>();
    k_final<<<(N_NODES * DIM / 4 + 255) / 256, 256>>>(out);
}

// round 16
// speedup vs baseline: 1.0819x; 1.0419x over previous
#include <cuda_runtime.h>
#include <cuda_bf16.h>
#include <math.h>
#include <stdint.h>

#define N_NODES 30000
#define DIM     512
#define NE      300000
#define ET      (NE + N_NODES)     // 330000 edges incl self-loops
#define MPAD    30080              // 235 * 128
#define NPADD   (MPAD * DIM)
#define SLOTS   64                 // payload slots per dst (max kept in-degree ~18)

// ---------------- scratch (static __device__, no allocations) ----------------
__device__ __nv_bfloat16 g_ah[NPADD];       // A hi (dropout applied)
__device__ __nv_bfloat16 g_al[NPADD];       // A lo
__device__ __nv_bfloat16 g_wh[DIM * DIM];   // W^T hi  [n, k]
__device__ __nv_bfloat16 g_wl[DIM * DIM];   // W^T lo
__device__ float    g_h[NPADD];
__device__ float    g_as[N_NODES];
__device__ float    g_ad[N_NODES];
__device__ float    g_s[N_NODES];
__device__ int      g_cnt[N_NODES];
__device__ int2     g_pay[(size_t)N_NODES * SLOTS];   // {src, ee*2.5f}
__device__ double   g_colsum[DIM];
__device__ double   g_sumsq;
__device__ float    g_mu[DIM];
__device__ float    g_inv;

// ---------------- threefry2x32 (JAX-exact, 20 rounds), constexpr-capable ----
__host__ __device__ constexpr unsigned rotl32(unsigned v, int d) {
    return (v << d) | (v >> (32 - d));
}

struct U2 { unsigned a, b; };

__host__ __device__ constexpr U2 threefry2x32(
    unsigned k0, unsigned k1, unsigned c0, unsigned c1)
{
    unsigned ks0 = k0, ks1 = k1, ks2 = k0 ^ k1 ^ 0x1BD11BDAu;
    unsigned x0 = c0 + ks0;
    unsigned x1 = c1 + ks1;

#define TF_R4(a,b,c,d) \
    x0 += x1; x1 = rotl32(x1, a); x1 ^= x0; \
    x0 += x1; x1 = rotl32(x1, b); x1 ^= x0; \
    x0 += x1; x1 = rotl32(x1, c); x1 ^= x0; \
    x0 += x1; x1 = rotl32(x1, d); x1 ^= x0;

    TF_R4(13,15,26,6)   x0 += ks1; x1 += ks2 + 1u;
    TF_R4(17,29,16,24)  x0 += ks2; x1 += ks0 + 2u;
    TF_R4(13,15,26,6)   x0 += ks0; x1 += ks1 + 3u;
    TF_R4(17,29,16,24)  x0 += ks1; x1 += ks2 + 4u;
    TF_R4(13,15,26,6)   x0 += ks2; x1 += ks0 + 5u;
#undef TF_R4
    return U2{x0, x1};
}

constexpr U2 KFEAT = threefry2x32(0u, 42u, 0u, 0u);
constexpr U2 KATT  = threefry2x32(0u, 42u, 0u, 1u);

__device__ __forceinline__ unsigned tf_bits(unsigned k0, unsigned k1, unsigned idx) {
    U2 r = threefry2x32(k0, k1, 0u, idx);
    return r.a ^ r.b;
}
// attention-dropout keep test (exact float compare as reference)
__device__ __forceinline__ bool att_keep(unsigned j) {
    unsigned bits = tf_bits(KATT.a, KATT.b, j);
    float u = __uint_as_float((bits >> 9) | 0x3f800000u) - 1.0f;
    return u < 0.4f;
}

__device__ __forceinline__ uint32_t smem_u32(const void* p) {
    uint32_t a;
    asm("{ .reg .u64 t; cvta.to.shared.u64 t, %1; cvt.u32.u64 %0, t; }"
        : "=r"(a) : "l"(p));
    return a;
}
__device__ __forceinline__ void cp16(uint32_t dst, const void* src) {
    asm volatile("cp.async.cg.shared.global [%0], [%1], 16;"
                 :: "r"(dst), "l"(src) : "memory");
}

// ---------------- kernels ----------------
// fused init + W transpose/split
__global__ void k_prep_w(const float* __restrict__ W) {
    int i = blockIdx.x * blockDim.x + threadIdx.x;
    if (i < DIM * DIM) {
        int n = i >> 9, k = i & (DIM - 1);
        float v = W[k * DIM + n];
        __nv_bfloat16 h = __float2bfloat16(v);
        g_wh[i] = h;
        g_wl[i] = __float2bfloat16(v - __bfloat162float(h));
    }
    if (i < N_NODES) {
        g_cnt[i] = 0; g_s[i] = 0.0f;
        g_as[i] = 0.0f; g_ad[i] = 0.0f;
    }
    if (i < DIM) { g_colsum[i] = 0.0; }
    if (i == 0)  { g_sumsq = 0.0; }
}

// fused feature-dropout + bf16 hi/lo split, 4 elems/thread (ILP on threefry)
__global__ void k_prep_a(const float* __restrict__ x) {
    unsigned t  = blockIdx.x * blockDim.x + threadIdx.x;
    unsigned i0 = t * 4;
    if (i0 >= (unsigned)NPADD) return;

    unsigned hh[2] = {0u, 0u}, ll[2] = {0u, 0u};
    if (i0 < (unsigned)(N_NODES * DIM)) {       // region is 4-divisible
        float4 xv = *(const float4*)(x + i0);
        float vs[4] = {xv.x, xv.y, xv.z, xv.w};
        unsigned mb[4];
#pragma unroll
        for (int j = 0; j < 4; j++) mb[j] = tf_bits(KFEAT.a, KFEAT.b, i0 + j);
#pragma unroll
        for (int j = 0; j < 4; j++) {
            // keep  <=>  u < 0.5  <=>  top bit of bits is 0
            float v = (mb[j] & 0x80000000u) ? 0.0f : vs[j] * 2.0f;
            __nv_bfloat16 h = __float2bfloat16(v);
            __nv_bfloat16 l = __float2bfloat16(v - __bfloat162float(h));
            unsigned hu = (unsigned)__bfloat16_as_ushort(h);
            unsigned lu = (unsigned)__bfloat16_as_ushort(l);
            hh[j >> 1] |= hu << ((j & 1) * 16);
            ll[j >> 1] |= lu << ((j & 1) * 16);
        }
    }
    *(uint2*)((unsigned short*)g_ah + i0) = make_uint2(hh[0], hh[1]);
    *(uint2*)((unsigned short*)g_al + i0) = make_uint2(ll[0], ll[1]);
}

// ---------------- mma.sync bf16 GEMM, single-loop 3-product -----------------
// CTA tile 128x128, 8 warps (2x4), warp tile 64x32, BK=32.
// Per K-chunk load Ah,Al,Wh,Wl once; acc += ah*wh + ah*wl + al*wh.
// Fused epilogue: h row-dots with att_src/att_dst -> g_as/g_ad (atomic).
#define LDT 40                      // padded smem lead dim (bf16 elems)
#define GBK 32
#define NCH (DIM / GBK)             // 16 chunks
#define TILE_B (128 * LDT * 2)      // 10240 B per tile
#define STG_B  (4 * TILE_B)         // Ah,Al,Bh,Bl per stage = 40960 B
#define SM_GEMM (2 * STG_B)         // 81920 B

__global__ void __launch_bounds__(256, 2) k_gemm_mma(
    const float* __restrict__ att_src,
    const float* __restrict__ att_dst)
{
    extern __shared__ char smem[];

    const int tid  = threadIdx.x;
    const int wid  = tid >> 5;
    const int lane = tid & 31;
    const int brow = blockIdx.y * 128;
    const int bcol = blockIdx.x * 128;
    const int wm   = (wid >> 2) * 64;
    const int wn   = (wid & 3) * 32;

    const int lr = tid >> 2;              // 0..63 (x2 -> 128 rows)
    const int lc = (tid & 3) * 8;         // bf16 col group

    const uint32_t s0 = smem_u32(smem);

    float acc[4][4][4];
#pragma unroll
    for (int mt = 0; mt < 4; mt++)
#pragma unroll
        for (int nt = 0; nt < 4; nt++)
#pragma unroll
            for (int c = 0; c < 4; c++) acc[mt][nt][c] = 0.0f;

    const int a_row  = wm + (lane & 15);
    const int a_koff = (lane >> 4) * 8;
    const int b_row  = wn + (lane & 15);

    auto load_chunk = [&](int c, int st) {
        int k0 = c * GBK;
        uint32_t base = s0 + st * STG_B;
#pragma unroll
        for (int it = 0; it < 2; it++) {
            int r = lr + it * 64;
            uint32_t off = (r * LDT + lc) * 2;
            size_t ga = (size_t)(brow + r) * DIM + k0 + lc;
            size_t gb = (size_t)(bcol + r) * DIM + k0 + lc;
            cp16(base + 0 * TILE_B + off, g_ah + ga);
            cp16(base + 1 * TILE_B + off, g_al + ga);
            cp16(base + 2 * TILE_B + off, g_wh + gb);
            cp16(base + 3 * TILE_B + off, g_wl + gb);
        }
    };

    load_chunk(0, 0);
    asm volatile("cp.async.commit_group;" ::: "memory");

    for (int c = 0; c < NCH; c++) {
        int st = c & 1;
        if (c + 1 < NCH) {
            asm volatile("cp.async.wait_group 0;" ::: "memory");
            __syncthreads();
            load_chunk(c + 1, st ^ 1);
            asm volatile("cp.async.commit_group;" ::: "memory");
        } else {
            asm volatile("cp.async.wait_group 0;" ::: "memory");
            __syncthreads();
        }

        const __nv_bfloat16* Ah = (const __nv_bfloat16*)(smem + st * STG_B);
        const __nv_bfloat16* Al = (const __nv_bfloat16*)(smem + st * STG_B + TILE_B);
        const __nv_bfloat16* Bh = (const __nv_bfloat16*)(smem + st * STG_B + 2 * TILE_B);
        const __nv_bfloat16* Bl = (const __nv_bfloat16*)(smem + st * STG_B + 3 * TILE_B);

#pragma unroll
        for (int ks = 0; ks < 2; ks++) {
            int k16 = ks * 16;
            uint32_t bh[4][2], bl[4][2];
#pragma unroll
            for (int nt2 = 0; nt2 < 2; nt2++) {
                uint32_t r0, r1, r2, r3;
                uint32_t addr = smem_u32(&Bh[(b_row + nt2 * 16) * LDT + k16 + a_koff]);
                asm volatile(
                    "ldmatrix.sync.aligned.m8n8.x4.shared.b16 {%0,%1,%2,%3}, [%4];"
                    : "=r"(r0), "=r"(r1), "=r"(r2), "=r"(r3) : "r"(addr));
                bh[2 * nt2][0] = r0; bh[2 * nt2 + 1][0] = r1;
                bh[2 * nt2][1] = r2; bh[2 * nt2 + 1][1] = r3;
                addr = smem_u32(&Bl[(b_row + nt2 * 16) * LDT + k16 + a_koff]);
                asm volatile(
                    "ldmatrix.sync.aligned.m8n8.x4.shared.b16 {%0,%1,%2,%3}, [%4];"
                    : "=r"(r0), "=r"(r1), "=r"(r2), "=r"(r3) : "r"(addr));
                bl[2 * nt2][0] = r0; bl[2 * nt2 + 1][0] = r1;
                bl[2 * nt2][1] = r2; bl[2 * nt2 + 1][1] = r3;
            }
            uint32_t a[4][4];
#pragma unroll
            for (int mt = 0; mt < 4; mt++) {
                uint32_t addr = smem_u32(&Ah[(a_row + mt * 16) * LDT + k16 + a_koff]);
                asm volatile(
                    "ldmatrix.sync.aligned.m8n8.x4.shared.b16 {%0,%1,%2,%3}, [%4];"
                    : "=r"(a[mt][0]), "=r"(a[mt][1]), "=r"(a[mt][2]), "=r"(a[mt][3])
                    : "r"(addr));
            }
#pragma unroll
            for (int mt = 0; mt < 4; mt++)
#pragma unroll
                for (int nt = 0; nt < 4; nt++) {
                    asm volatile(
                        "mma.sync.aligned.m16n8k16.row.col.f32.bf16.bf16.f32 "
                        "{%0,%1,%2,%3}, {%4,%5,%6,%7}, {%8,%9}, {%0,%1,%2,%3};"
                        : "+f"(acc[mt][nt][0]), "+f"(acc[mt][nt][1]),
                          "+f"(acc[mt][nt][2]), "+f"(acc[mt][nt][3])
                        : "r"(a[mt][0]), "r"(a[mt][1]), "r"(a[mt][2]), "r"(a[mt][3]),
                          "r"(bh[nt][0]), "r"(bh[nt][1]));
                    asm volatile(
                        "mma.sync.aligned.m16n8k16.row.col.f32.bf16.bf16.f32 "
                        "{%0,%1,%2,%3}, {%4,%5,%6,%7}, {%8,%9}, {%0,%1,%2,%3};"
                        : "+f"(acc[mt][nt][0]), "+f"(acc[mt][nt][1]),
                          "+f"(acc[mt][nt][2]), "+f"(acc[mt][nt][3])
                        : "r"(a[mt][0]), "r"(a[mt][1]), "r"(a[mt][2]), "r"(a[mt][3]),
                          "r"(bl[nt][0]), "r"(bl[nt][1]));
                }
#pragma unroll
            for (int mt = 0; mt < 4; mt++) {
                uint32_t addr = smem_u32(&Al[(a_row + mt * 16) * LDT + k16 + a_koff]);
                asm volatile(
                    "ldmatrix.sync.aligned.m8n8.x4.shared.b16 {%0,%1,%2,%3}, [%4];"
                    : "=r"(a[mt][0]), "=r"(a[mt][1]), "=r"(a[mt][2]), "=r"(a[mt][3])
                    : "r"(addr));
            }
#pragma unroll
            for (int mt = 0; mt < 4; mt++)
#pragma unroll
                for (int nt = 0; nt < 4; nt++) {
                    asm volatile(
                        "mma.sync.aligned.m16n8k16.row.col.f32.bf16.bf16.f32 "
                        "{%0,%1,%2,%3}, {%4,%5,%6,%7}, {%8,%9}, {%0,%1,%2,%3};"
                        : "+f"(acc[mt][nt][0]), "+f"(acc[mt][nt][1]),
                          "+f"(acc[mt][nt][2]), "+f"(acc[mt][nt][3])
                        : "r"(a[mt][0]), "r"(a[mt][1]), "r"(a[mt][2]), "r"(a[mt][3]),
                          "r"(bh[nt][0]), "r"(bh[nt][1]));
                }
        }
        if (c + 1 < NCH) __syncthreads();
        // barrier orders "all warps finished reading stage st" before the
        // NEXT iteration's cp.async writes into it.
    }

    // epilogue: write fp32 result + fused att dot products
    const int group = lane >> 2;
    const int tg    = lane & 3;

    float as0[4], as1[4], ad0[4], ad1[4];
#pragma unroll
    for (int nt = 0; nt < 4; nt++) {
        int col = bcol + wn + nt * 8 + tg * 2;
        as0[nt] = att_src[col];  as1[nt] = att_src[col + 1];
        ad0[nt] = att_dst[col];  ad1[nt] = att_dst[col + 1];
    }

#pragma unroll
    for (int mt = 0; mt < 4; mt++) {
        int m0 = brow + wm + mt * 16 + group;
        float v0s = 0.f, v8s = 0.f, v0d = 0.f, v8d = 0.f;
#pragma unroll
        for (int nt = 0; nt < 4; nt++) {
            int col = bcol + wn + nt * 8 + tg * 2;
            *(float2*)(g_h + (size_t)m0 * DIM + col) =
                make_float2(acc[mt][nt][0], acc[mt][nt][1]);
            *(float2*)(g_h + (size_t)(m0 + 8) * DIM + col) =
                make_float2(acc[mt][nt][2], acc[mt][nt][3]);
            v0s += acc[mt][nt][0] * as0[nt] + acc[mt][nt][1] * as1[nt];
            v8s += acc[mt][nt][2] * as0[nt] + acc[mt][nt][3] * as1[nt];
            v0d += acc[mt][nt][0] * ad0[nt] + acc[mt][nt][1] * ad1[nt];
            v8d += acc[mt][nt][2] * ad0[nt] + acc[mt][nt][3] * ad1[nt];
        }
#pragma unroll
        for (int o = 1; o <= 2; o <<= 1) {
            v0s += __shfl_xor_sync(0xffffffffu, v0s, o);
            v8s += __shfl_xor_sync(0xffffffffu, v8s, o);
            v0d += __shfl_xor_sync(0xffffffffu, v0d, o);
            v8d += __shfl_xor_sync(0xffffffffu, v8d, o);
        }
        if (tg == 0) {
            if (m0 < N_NODES) {
                atomicAdd(&g_as[m0], v0s);
                atomicAdd(&g_ad[m0], v0d);
            }
            if (m0 + 8 < N_NODES) {
                atomicAdd(&g_as[m0 + 8], v8s);
                atomicAdd(&g_ad[m0 + 8], v8d);
            }
        }
    }
}

// single-pass edge pipeline: logit -> exp -> softmax denom -> keep -> slot write
__global__ void k_edge(const int* __restrict__ ei) {
    int j = blockIdx.x * blockDim.x + threadIdx.x;
    if (j >= ET) return;
    int src = (j < NE) ? ei[j]      : (j - NE);
    int dst = (j < NE) ? ei[NE + j] : (j - NE);
    float e = g_as[src] + g_ad[dst];
    e = (e >= 0.0f) ? e : 0.2f * e;                 // LeakyReLU(0.2)
    float ee = __expf(e);
    atomicAdd(&g_s[dst], ee);
    if (att_keep((unsigned)j)) {
        int pos = atomicAdd(&g_cnt[dst], 1);
        g_pay[(size_t)dst * SLOTS + pos] = make_int2(src, __float_as_int(ee * 2.5f));
    }
}

// block per dst node; 128 threads x float4 = 512 cols; slotted payload bin
__global__ void __launch_bounds__(128) k_agg(
    const float* __restrict__ bias,
    float* __restrict__ out)
{
    int dst = blockIdx.x;
    int c   = threadIdx.x * 4;
    float inv = 1.0f / (g_s[dst] + 1e-16f);
    float4 acc = make_float4(0.f, 0.f, 0.f, 0.f);
    int n = g_cnt[dst];
    const int2* pp = g_pay + (size_t)dst * SLOTS;
    for (int p = 0; p < n; p++) {
        int2 rec = pp[p];
        float w = __int_as_float(rec.y) * inv;
        float4 hv = *(const float4*)(g_h + (size_t)rec.x * DIM + c);
        acc.x = fmaf(w, hv.x, acc.x);
        acc.y = fmaf(w, hv.y, acc.y);
        acc.z = fmaf(w, hv.z, acc.z);
        acc.w = fmaf(w, hv.w, acc.w);
    }
    float4 bv = *(const float4*)(bias + c);
    acc.x += bv.x; acc.y += bv.y; acc.z += bv.z; acc.w += bv.w;
    *(float4*)(out + (size_t)dst * DIM + c) = acc;
}

// column sums + total sum of squares (for PairNorm)
#define CM_ROWS 235
__global__ void __launch_bounds__(256) k_colmean(const float* __restrict__ out) {
    __shared__ double ssq_sh[256];
    int tid = threadIdx.x;
    int r0 = blockIdx.x * CM_ROWS;
    int r1 = min(N_NODES, r0 + CM_ROWS);
    float s1 = 0.0f, s2 = 0.0f;
    double ssq = 0.0;
    for (int r = r0; r < r1; r++) {
        float v1 = out[(size_t)r * DIM + tid];
        float v2 = out[(size_t)r * DIM + tid + 256];
        s1 += v1; s2 += v2;
        ssq += (double)v1 * v1 + (double)v2 * v2;
    }
    atomicAdd(&g_colsum[tid],       (double)s1);
    atomicAdd(&g_colsum[tid + 256], (double)s2);
    ssq_sh[tid] = ssq;
    __syncthreads();
    for (int o = 128; o > 0; o >>= 1) {
        if (tid < o) ssq_sh[tid] += ssq_sh[tid + o];
        __syncthreads();
    }
    if (tid == 0) atomicAdd(&g_sumsq, ssq_sh[0]);
}

__global__ void k_stats() {
    __shared__ double sh[512];
    int t = threadIdx.x;
    double mu = g_colsum[t] / (double)N_NODES;
    g_mu[t] = (float)mu;
    sh[t] = mu * mu;
    __syncthreads();
    for (int o = 256; o > 0; o >>= 1) {
        if (t < o) sh[t] += sh[t + o];
        __syncthreads();
    }
    if (t == 0) {
        double var = g_sumsq / (double)N_NODES - sh[0];
        g_inv = (float)(1.0 / sqrt(1e-6 + var));
    }
}

__global__ void k_final(float* __restrict__ out) {
    unsigned i = (blockIdx.x * blockDim.x + threadIdx.x) * 4;
    if (i >= (unsigned)(N_NODES * DIM)) return;
    float4 v  = *(const float4*)(out + i);
    float4 mu = *(const float4*)(g_mu + (i & (DIM - 1)));
    float inv = g_inv;
    v.x = fmaxf((v.x - mu.x) * inv, 0.0f);
    v.y = fmaxf((v.y - mu.y) * inv, 0.0f);
    v.z = fmaxf((v.z - mu.z) * inv, 0.0f);
    v.w = fmaxf((v.w - mu.w) * inv, 0.0f);
    *(float4*)(out + i) = v;
}

// ---------------- launch ----------------
extern "C" void kernel_launch(void* const* d_in, const int* in_sizes, int n_in,
                              void* d_out, int out_size)
{
    const float* x       = (const float*)d_in[0];
    const int*   ei      = (const int*)  d_in[1];
    const float* W       = (const float*)d_in[2];
    const float* att_src = (const float*)d_in[3];
    const float* att_dst = (const float*)d_in[4];
    const float* bias    = (const float*)d_in[5];
    float*       out     = (float*)d_out;
    (void)in_sizes; (void)n_in; (void)out_size;

    cudaFuncSetAttribute(k_gemm_mma,
                         cudaFuncAttributeMaxDynamicSharedMemorySize, SM_GEMM);

    k_prep_w<<<(DIM * DIM + 255) / 256, 256>>>(W);
    k_prep_a<<<(NPADD / 4 + 255) / 256, 256>>>(x);
    k_gemm_mma<<<dim3(4, 235), 256, SM_GEMM>>>(att_src, att_dst);
    k_edge<<<(ET + 255) / 256, 256>>>(ei);
    k_agg<<<N_NODES, 128>>>(bias, out);
    k_colmean<<<(N_NODES + CM_ROWS - 1) / CM_ROWS, 256>>>(out);
    k_stats<<<1, 512>>>();
    k_final<<<(N_NODES * DIM / 4 + 255) / 256, 256>>>(out);
}

// round 17
// speedup vs baseline: 1.1002x; 1.0169x over previous
#include <cuda_runtime.h>
#include <cuda_bf16.h>
#include <math.h>
#include <stdint.h>

#define N_NODES 30000
#define DIM     512
#define NE      300000
#define ET      (NE + N_NODES)     // 330000 edges incl self-loops
#define MPAD    30080              // 235 * 128
#define NPADD   (MPAD * DIM)
#define SLOTS   64                 // payload slots per dst (max kept in-degree ~18)

// ---------------- scratch (static __device__, no allocations) ----------------
__device__ __nv_bfloat16 g_ah[NPADD];       // A hi (dropout applied)
__device__ __nv_bfloat16 g_al[NPADD];       // A lo
__device__ __nv_bfloat16 g_wh[DIM * DIM];   // W^T hi  [n, k]
__device__ __nv_bfloat16 g_wl[DIM * DIM];   // W^T lo
__device__ float    g_h[NPADD];
__device__ float    g_as[N_NODES];
__device__ float    g_ad[N_NODES];
__device__ float    g_s[N_NODES];
__device__ int      g_cnt[N_NODES];
__device__ int2     g_pay[(size_t)N_NODES * SLOTS];   // {src, ee*2.5f}
__device__ double   g_colsum[DIM];
__device__ double   g_sumsq;
__device__ float    g_mu[DIM];
__device__ float    g_inv;
__device__ int      g_done;

// ---------------- threefry2x32 (JAX-exact, 20 rounds), constexpr-capable ----
__host__ __device__ constexpr unsigned rotl32(unsigned v, int d) {
    return (v << d) | (v >> (32 - d));
}

struct U2 { unsigned a, b; };

__host__ __device__ constexpr U2 threefry2x32(
    unsigned k0, unsigned k1, unsigned c0, unsigned c1)
{
    unsigned ks0 = k0, ks1 = k1, ks2 = k0 ^ k1 ^ 0x1BD11BDAu;
    unsigned x0 = c0 + ks0;
    unsigned x1 = c1 + ks1;

#define TF_R4(a,b,c,d) \
    x0 += x1; x1 = rotl32(x1, a); x1 ^= x0; \
    x0 += x1; x1 = rotl32(x1, b); x1 ^= x0; \
    x0 += x1; x1 = rotl32(x1, c); x1 ^= x0; \
    x0 += x1; x1 = rotl32(x1, d); x1 ^= x0;

    TF_R4(13,15,26,6)   x0 += ks1; x1 += ks2 + 1u;
    TF_R4(17,29,16,24)  x0 += ks2; x1 += ks0 + 2u;
    TF_R4(13,15,26,6)   x0 += ks0; x1 += ks1 + 3u;
    TF_R4(17,29,16,24)  x0 += ks1; x1 += ks2 + 4u;
    TF_R4(13,15,26,6)   x0 += ks2; x1 += ks0 + 5u;
#undef TF_R4
    return U2{x0, x1};
}

constexpr U2 KFEAT = threefry2x32(0u, 42u, 0u, 0u);
constexpr U2 KATT  = threefry2x32(0u, 42u, 0u, 1u);

__device__ __forceinline__ unsigned tf_bits(unsigned k0, unsigned k1, unsigned idx) {
    U2 r = threefry2x32(k0, k1, 0u, idx);
    return r.a ^ r.b;
}
// attention-dropout keep test (exact float compare as reference)
__device__ __forceinline__ bool att_keep(unsigned j) {
    unsigned bits = tf_bits(KATT.a, KATT.b, j);
    float u = __uint_as_float((bits >> 9) | 0x3f800000u) - 1.0f;
    return u < 0.4f;
}

__device__ __forceinline__ uint32_t smem_u32(const void* p) {
    uint32_t a;
    asm("{ .reg .u64 t; cvta.to.shared.u64 t, %1; cvt.u32.u64 %0, t; }"
        : "=r"(a) : "l"(p));
    return a;
}
__device__ __forceinline__ void cp16(uint32_t dst, const void* src) {
    asm volatile("cp.async.cg.shared.global [%0], [%1], 16;"
                 :: "r"(dst), "l"(src) : "memory");
}

// ---------------- kernels ----------------
// fused: init + W transpose/split + feature-dropout/bf16-split of x
__global__ void k_prep(const float* __restrict__ x, const float* __restrict__ W) {
    unsigned t = blockIdx.x * blockDim.x + threadIdx.x;

    // side work on the first blocks (grid is sized by the x sweep: 960k threads)
    if (t < DIM * DIM) {
        int n = t >> 9, k = t & (DIM - 1);
        float v = W[k * DIM + n];
        __nv_bfloat16 h = __float2bfloat16(v);
        g_wh[t] = h;
        g_wl[t] = __float2bfloat16(v - __bfloat162float(h));
    }
    if (t < N_NODES) {
        g_cnt[t] = 0; g_s[t] = 0.0f;
        g_as[t] = 0.0f; g_ad[t] = 0.0f;
    }
    if (t < DIM) { g_colsum[t] = 0.0; }
    if (t == 0)  { g_sumsq = 0.0; g_done = 0; }

    unsigned i0 = t * 4;
    if (i0 >= (unsigned)NPADD) return;

    unsigned hh[2] = {0u, 0u}, ll[2] = {0u, 0u};
    if (i0 < (unsigned)(N_NODES * DIM)) {       // region is 4-divisible
        float4 xv = *(const float4*)(x + i0);
        float vs[4] = {xv.x, xv.y, xv.z, xv.w};
        unsigned mb[4];
#pragma unroll
        for (int j = 0; j < 4; j++) mb[j] = tf_bits(KFEAT.a, KFEAT.b, i0 + j);
#pragma unroll
        for (int j = 0; j < 4; j++) {
            // keep  <=>  u < 0.5  <=>  top bit of bits is 0
            float v = (mb[j] & 0x80000000u) ? 0.0f : vs[j] * 2.0f;
            __nv_bfloat16 h = __float2bfloat16(v);
            __nv_bfloat16 l = __float2bfloat16(v - __bfloat162float(h));
            unsigned hu = (unsigned)__bfloat16_as_ushort(h);
            unsigned lu = (unsigned)__bfloat16_as_ushort(l);
            hh[j >> 1] |= hu << ((j & 1) * 16);
            ll[j >> 1] |= lu << ((j & 1) * 16);
        }
    }
    *(uint2*)((unsigned short*)g_ah + i0) = make_uint2(hh[0], hh[1]);
    *(uint2*)((unsigned short*)g_al + i0) = make_uint2(ll[0], ll[1]);
}

// ---------------- mma.sync bf16 GEMM, single-loop 3-product -----------------
// CTA tile 128x128, 8 warps (2x4), warp tile 64x32, BK=32.
// Per K-chunk load Ah,Al,Wh,Wl once; acc += ah*wh + ah*wl + al*wh.
// Fused epilogue: h row-dots with att_src/att_dst -> g_as/g_ad (atomic).
#define LDT 40                      // padded smem lead dim (bf16 elems)
#define GBK 32
#define NCH (DIM / GBK)             // 16 chunks
#define TILE_B (128 * LDT * 2)      // 10240 B per tile
#define STG_B  (4 * TILE_B)         // Ah,Al,Bh,Bl per stage = 40960 B
#define SM_GEMM (2 * STG_B)         // 81920 B

__global__ void __launch_bounds__(256, 2) k_gemm_mma(
    const float* __restrict__ att_src,
    const float* __restrict__ att_dst)
{
    extern __shared__ char smem[];

    const int tid  = threadIdx.x;
    const int wid  = tid >> 5;
    const int lane = tid & 31;
    const int brow = blockIdx.y * 128;
    const int bcol = blockIdx.x * 128;
    const int wm   = (wid >> 2) * 64;
    const int wn   = (wid & 3) * 32;

    const int lr = tid >> 2;              // 0..63 (x2 -> 128 rows)
    const int lc = (tid & 3) * 8;         // bf16 col group

    const uint32_t s0 = smem_u32(smem);

    float acc[4][4][4];
#pragma unroll
    for (int mt = 0; mt < 4; mt++)
#pragma unroll
        for (int nt = 0; nt < 4; nt++)
#pragma unroll
            for (int c = 0; c < 4; c++) acc[mt][nt][c] = 0.0f;

    const int a_row  = wm + (lane & 15);
    const int a_koff = (lane >> 4) * 8;
    const int b_row  = wn + (lane & 15);

    auto load_chunk = [&](int c, int st) {
        int k0 = c * GBK;
        uint32_t base = s0 + st * STG_B;
#pragma unroll
        for (int it = 0; it < 2; it++) {
            int r = lr + it * 64;
            uint32_t off = (r * LDT + lc) * 2;
            size_t ga = (size_t)(brow + r) * DIM + k0 + lc;
            size_t gb = (size_t)(bcol + r) * DIM + k0 + lc;
            cp16(base + 0 * TILE_B + off, g_ah + ga);
            cp16(base + 1 * TILE_B + off, g_al + ga);
            cp16(base + 2 * TILE_B + off, g_wh + gb);
            cp16(base + 3 * TILE_B + off, g_wl + gb);
        }
    };

    load_chunk(0, 0);
    asm volatile("cp.async.commit_group;" ::: "memory");

    for (int c = 0; c < NCH; c++) {
        int st = c & 1;
        if (c + 1 < NCH) {
            asm volatile("cp.async.wait_group 0;" ::: "memory");
            __syncthreads();
            load_chunk(c + 1, st ^ 1);
            asm volatile("cp.async.commit_group;" ::: "memory");
        } else {
            asm volatile("cp.async.wait_group 0;" ::: "memory");
            __syncthreads();
        }
        // note: the barrier above (next iteration) also orders stage reuse;
        // no end-of-loop barrier needed.

        const __nv_bfloat16* Ah = (const __nv_bfloat16*)(smem + st * STG_B);
        const __nv_bfloat16* Al = (const __nv_bfloat16*)(smem + st * STG_B + TILE_B);
        const __nv_bfloat16* Bh = (const __nv_bfloat16*)(smem + st * STG_B + 2 * TILE_B);
        const __nv_bfloat16* Bl = (const __nv_bfloat16*)(smem + st * STG_B + 3 * TILE_B);

#pragma unroll
        for (int ks = 0; ks < 2; ks++) {
            int k16 = ks * 16;
            uint32_t bh[4][2], bl[4][2];
#pragma unroll
            for (int nt2 = 0; nt2 < 2; nt2++) {
                uint32_t r0, r1, r2, r3;
                uint32_t addr = smem_u32(&Bh[(b_row + nt2 * 16) * LDT + k16 + a_koff]);
                asm volatile(
                    "ldmatrix.sync.aligned.m8n8.x4.shared.b16 {%0,%1,%2,%3}, [%4];"
                    : "=r"(r0), "=r"(r1), "=r"(r2), "=r"(r3) : "r"(addr));
                bh[2 * nt2][0] = r0; bh[2 * nt2 + 1][0] = r1;
                bh[2 * nt2][1] = r2; bh[2 * nt2 + 1][1] = r3;
                addr = smem_u32(&Bl[(b_row + nt2 * 16) * LDT + k16 + a_koff]);
                asm volatile(
                    "ldmatrix.sync.aligned.m8n8.x4.shared.b16 {%0,%1,%2,%3}, [%4];"
                    : "=r"(r0), "=r"(r1), "=r"(r2), "=r"(r3) : "r"(addr));
                bl[2 * nt2][0] = r0; bl[2 * nt2 + 1][0] = r1;
                bl[2 * nt2][1] = r2; bl[2 * nt2 + 1][1] = r3;
            }
            uint32_t a[4][4];
#pragma unroll
            for (int mt = 0; mt < 4; mt++) {
                uint32_t addr = smem_u32(&Ah[(a_row + mt * 16) * LDT + k16 + a_koff]);
                asm volatile(
                    "ldmatrix.sync.aligned.m8n8.x4.shared.b16 {%0,%1,%2,%3}, [%4];"
                    : "=r"(a[mt][0]), "=r"(a[mt][1]), "=r"(a[mt][2]), "=r"(a[mt][3])
                    : "r"(addr));
            }
#pragma unroll
            for (int mt = 0; mt < 4; mt++)
#pragma unroll
                for (int nt = 0; nt < 4; nt++) {
                    asm volatile(
                        "mma.sync.aligned.m16n8k16.row.col.f32.bf16.bf16.f32 "
                        "{%0,%1,%2,%3}, {%4,%5,%6,%7}, {%8,%9}, {%0,%1,%2,%3};"
                        : "+f"(acc[mt][nt][0]), "+f"(acc[mt][nt][1]),
                          "+f"(acc[mt][nt][2]), "+f"(acc[mt][nt][3])
                        : "r"(a[mt][0]), "r"(a[mt][1]), "r"(a[mt][2]), "r"(a[mt][3]),
                          "r"(bh[nt][0]), "r"(bh[nt][1]));
                    asm volatile(
                        "mma.sync.aligned.m16n8k16.row.col.f32.bf16.bf16.f32 "
                        "{%0,%1,%2,%3}, {%4,%5,%6,%7}, {%8,%9}, {%0,%1,%2,%3};"
                        : "+f"(acc[mt][nt][0]), "+f"(acc[mt][nt][1]),
                          "+f"(acc[mt][nt][2]), "+f"(acc[mt][nt][3])
                        : "r"(a[mt][0]), "r"(a[mt][1]), "r"(a[mt][2]), "r"(a[mt][3]),
                          "r"(bl[nt][0]), "r"(bl[nt][1]));
                }
#pragma unroll
            for (int mt = 0; mt < 4; mt++) {
                uint32_t addr = smem_u32(&Al[(a_row + mt * 16) * LDT + k16 + a_koff]);
                asm volatile(
                    "ldmatrix.sync.aligned.m8n8.x4.shared.b16 {%0,%1,%2,%3}, [%4];"
                    : "=r"(a[mt][0]), "=r"(a[mt][1]), "=r"(a[mt][2]), "=r"(a[mt][3])
                    : "r"(addr));
            }
#pragma unroll
            for (int mt = 0; mt < 4; mt++)
#pragma unroll
                for (int nt = 0; nt < 4; nt++) {
                    asm volatile(
                        "mma.sync.aligned.m16n8k16.row.col.f32.bf16.bf16.f32 "
                        "{%0,%1,%2,%3}, {%4,%5,%6,%7}, {%8,%9}, {%0,%1,%2,%3};"
                        : "+f"(acc[mt][nt][0]), "+f"(acc[mt][nt][1]),
                          "+f"(acc[mt][nt][2]), "+f"(acc[mt][nt][3])
                        : "r"(a[mt][0]), "r"(a[mt][1]), "r"(a[mt][2]), "r"(a[mt][3]),
                          "r"(bh[nt][0]), "r"(bh[nt][1]));
                }
        }
    }

    // epilogue: write fp32 result + fused att dot products
    const int group = lane >> 2;
    const int tg    = lane & 3;

    float as0[4], as1[4], ad0[4], ad1[4];
#pragma unroll
    for (int nt = 0; nt < 4; nt++) {
        int col = bcol + wn + nt * 8 + tg * 2;
        as0[nt] = att_src[col];  as1[nt] = att_src[col + 1];
        ad0[nt] = att_dst[col];  ad1[nt] = att_dst[col + 1];
    }

#pragma unroll
    for (int mt = 0; mt < 4; mt++) {
        int m0 = brow + wm + mt * 16 + group;
        float v0s = 0.f, v8s = 0.f, v0d = 0.f, v8d = 0.f;
#pragma unroll
        for (int nt = 0; nt < 4; nt++) {
            int col = bcol + wn + nt * 8 + tg * 2;
            *(float2*)(g_h + (size_t)m0 * DIM + col) =
                make_float2(acc[mt][nt][0], acc[mt][nt][1]);
            *(float2*)(g_h + (size_t)(m0 + 8) * DIM + col) =
                make_float2(acc[mt][nt][2], acc[mt][nt][3]);
            v0s += acc[mt][nt][0] * as0[nt] + acc[mt][nt][1] * as1[nt];
            v8s += acc[mt][nt][2] * as0[nt] + acc[mt][nt][3] * as1[nt];
            v0d += acc[mt][nt][0] * ad0[nt] + acc[mt][nt][1] * ad1[nt];
            v8d += acc[mt][nt][2] * ad0[nt] + acc[mt][nt][3] * ad1[nt];
        }
#pragma unroll
        for (int o = 1; o <= 2; o <<= 1) {
            v0s += __shfl_xor_sync(0xffffffffu, v0s, o);
            v8s += __shfl_xor_sync(0xffffffffu, v8s, o);
            v0d += __shfl_xor_sync(0xffffffffu, v0d, o);
            v8d += __shfl_xor_sync(0xffffffffu, v8d, o);
        }
        if (tg == 0) {
            if (m0 < N_NODES) {
                atomicAdd(&g_as[m0], v0s);
                atomicAdd(&g_ad[m0], v0d);
            }
            if (m0 + 8 < N_NODES) {
                atomicAdd(&g_as[m0 + 8], v8s);
                atomicAdd(&g_ad[m0 + 8], v8d);
            }
        }
    }
}

// single-pass edge pipeline: logit -> exp -> softmax denom -> keep -> slot write
__global__ void k_edge(const int* __restrict__ ei) {
    int j = blockIdx.x * blockDim.x + threadIdx.x;
    if (j >= ET) return;
    int src = (j < NE) ? ei[j]      : (j - NE);
    int dst = (j < NE) ? ei[NE + j] : (j - NE);
    float e = g_as[src] + g_ad[dst];
    e = (e >= 0.0f) ? e : 0.2f * e;                 // LeakyReLU(0.2)
    float ee = __expf(e);
    atomicAdd(&g_s[dst], ee);
    if (att_keep((unsigned)j)) {
        int pos = atomicAdd(&g_cnt[dst], 1);
        g_pay[(size_t)dst * SLOTS + pos] = make_int2(src, __float_as_int(ee * 2.5f));
    }
}

// block per dst node; 128 threads x float4 = 512 cols; slotted payload bin
__global__ void __launch_bounds__(128) k_agg(
    const float* __restrict__ bias,
    float* __restrict__ out)
{
    int dst = blockIdx.x;
    int c   = threadIdx.x * 4;
    float inv = 1.0f / (g_s[dst] + 1e-16f);
    float4 acc = make_float4(0.f, 0.f, 0.f, 0.f);
    int n = g_cnt[dst];
    const int2* pp = g_pay + (size_t)dst * SLOTS;
    for (int p = 0; p < n; p++) {
        int2 rec = pp[p];
        float w = __int_as_float(rec.y) * inv;
        float4 hv = *(const float4*)(g_h + (size_t)rec.x * DIM + c);
        acc.x = fmaf(w, hv.x, acc.x);
        acc.y = fmaf(w, hv.y, acc.y);
        acc.z = fmaf(w, hv.z, acc.z);
        acc.w = fmaf(w, hv.w, acc.w);
    }
    float4 bv = *(const float4*)(bias + c);
    acc.x += bv.x; acc.y += bv.y; acc.z += bv.z; acc.w += bv.w;
    *(float4*)(out + (size_t)dst * DIM + c) = acc;
}

// column sums + total sum of squares (for PairNorm) + fused stats (last block)
#define CM_ROWS 235
#define CM_GRID ((N_NODES + CM_ROWS - 1) / CM_ROWS)
__global__ void __launch_bounds__(256) k_colmean(const float* __restrict__ out) {
    __shared__ double ssq_sh[256];
    __shared__ int last;
    int tid = threadIdx.x;
    int r0 = blockIdx.x * CM_ROWS;
    int r1 = min(N_NODES, r0 + CM_ROWS);
    float s1 = 0.0f, s2 = 0.0f;
    double ssq = 0.0;
    for (int r = r0; r < r1; r++) {
        float v1 = out[(size_t)r * DIM + tid];
        float v2 = out[(size_t)r * DIM + tid + 256];
        s1 += v1; s2 += v2;
        ssq += (double)v1 * v1 + (double)v2 * v2;
    }
    atomicAdd(&g_colsum[tid],       (double)s1);
    atomicAdd(&g_colsum[tid + 256], (double)s2);
    ssq_sh[tid] = ssq;
    __syncthreads();
    for (int o = 128; o > 0; o >>= 1) {
        if (tid < o) ssq_sh[tid] += ssq_sh[tid + o];
        __syncthreads();
    }
    if (tid == 0) {
        atomicAdd(&g_sumsq, ssq_sh[0]);
        __threadfence();
        last = (atomicAdd(&g_done, 1) == CM_GRID - 1) ? 1 : 0;
    }
    __syncthreads();
    if (!last) return;

    // fused stats: this is the last block; all colsum/sumsq contributions done
    double mu0 = g_colsum[tid]       / (double)N_NODES;
    double mu1 = g_colsum[tid + 256] / (double)N_NODES;
    g_mu[tid]       = (float)mu0;
    g_mu[tid + 256] = (float)mu1;
    ssq_sh[tid] = mu0 * mu0 + mu1 * mu1;
    __syncthreads();
    for (int o = 128; o > 0; o >>= 1) {
        if (tid < o) ssq_sh[tid] += ssq_sh[tid + o];
        __syncthreads();
    }
    if (tid == 0) {
        double var = g_sumsq / (double)N_NODES - ssq_sh[0];
        g_inv = (float)(1.0 / sqrt(1e-6 + var));
    }
}

__global__ void k_final(float* __restrict__ out) {
    unsigned i = (blockIdx.x * blockDim.x + threadIdx.x) * 4;
    if (i >= (unsigned)(N_NODES * DIM)) return;
    float4 v  = *(const float4*)(out + i);
    float4 mu = *(const float4*)(g_mu + (i & (DIM - 1)));
    float inv = g_inv;
    v.x = fmaxf((v.x - mu.x) * inv, 0.0f);
    v.y = fmaxf((v.y - mu.y) * inv, 0.0f);
    v.z = fmaxf((v.z - mu.z) * inv, 0.0f);
    v.w = fmaxf((v.w - mu.w) * inv, 0.0f);
    *(float4*)(out + i) = v;
}

// ---------------- launch ----------------
extern "C" void kernel_launch(void* const* d_in, const int* in_sizes, int n_in,
                              void* d_out, int out_size)
{
    const float* x       = (const float*)d_in[0];
    const int*   ei      = (const int*)  d_in[1];
    const float* W       = (const float*)d_in[2];
    const float* att_src = (const float*)d_in[3];
    const float* att_dst = (const float*)d_in[4];
    const float* bias    = (const float*)d_in[5];
    float*       out     = (float*)d_out;
    (void)in_sizes; (void)n_in; (void)out_size;

    cudaFuncSetAttribute(k_gemm_mma,
                         cudaFuncAttributeMaxDynamicSharedMemorySize, SM_GEMM);

    k_prep<<<(NPADD / 4 + 255) / 256, 256>>>(x, W);
    k_gemm_mma<<<dim3(4, 235), 256, SM_GEMM>>>(att_src, att_dst);
    k_edge<<<(ET + 255) / 256, 256>>>(ei);
    k_agg<<<N_NODES, 128>>>(bias, out);
    k_colmean<<<CM_GRID, 256>>>(out);
    k_final<<<(N_NODES * DIM / 4 + 255) / 256, 256>>>(out);
}